// round 8
// baseline (speedup 1.0000x reference)
#include <cuda_runtime.h>
#include <cuda_bf16.h>
#include <math.h>

// ---------------------------------------------------------------------------
// Problem constants
// ---------------------------------------------------------------------------
#define BATCH 32
#define CIN   3
#define HIMG  128
#define WIMG  128
#define PSZ   16
#define EMB   768
#define DH    192
#define ROWS  2048         // BATCH * 64
#define HW1   16384
#define HW2   4096
#define HC2   2048

typedef unsigned long long u64;

// ---------------------------------------------------------------------------
// f32x2 helpers (FFMA2 path — exact fp32, 2x FMA throughput on sm_103a)
// ---------------------------------------------------------------------------
__device__ __forceinline__ u64 pk2(float lo, float hi) {
    u64 r; asm("mov.b64 %0, {%1,%2};" : "=l"(r) : "f"(lo), "f"(hi)); return r;
}
__device__ __forceinline__ void fma2(u64& d, u64 a, u64 b) {
    asm("fma.rn.f32x2 %0, %1, %2, %0;" : "+l"(d) : "l"(a), "l"(b));
}
__device__ __forceinline__ float2 upk2(u64 v) {
    float2 f; asm("mov.b64 {%0,%1}, %2;" : "=f"(f.x), "=f"(f.y) : "l"(v)); return f;
}
// LDS.128 into a u64 pair (requires 16B-aligned shared address)
__device__ __forceinline__ void lds_v2b64(u64& lo, u64& hi, const void* p) {
    unsigned saddr = (unsigned)__cvta_generic_to_shared(p);
    asm("ld.shared.v2.b64 {%0,%1}, [%2];" : "=l"(lo), "=l"(hi) : "r"(saddr));
}

// ---------------------------------------------------------------------------
// Scratch (device globals; no runtime allocation allowed)
// ---------------------------------------------------------------------------
__device__ float g_f1  [ROWS * HW1];
__device__ float g_y1  [ROWS * HW1];
__device__ float g_pool[ROWS * HW2];
__device__ float g_f2  [ROWS * HW2];
__device__ float g_y2  [ROWS * HW2];
__device__ float g_t   [ROWS * EMB];
__device__ float g_qkv [ROWS * 3 * EMB];
__device__ float g_att [ROWS * EMB];
__device__ float g_o   [ROWS * EMB];
__device__ float g_h1  [ROWS * HC2];
__device__ float g_tp  [ROWS * 4];
__device__ float g_par [ROWS * 6];
__device__ float g_part[3 * ROWS * EMB];   // split-K partials (split<=3, N<=768)

// ---------------------------------------------------------------------------
// SGEMM v5: C[M,N] = A[M,K] @ B[N,K]^T (+bias,+relu).
// A stored DUPLICATED in smem (each value twice) so FFMA2 A-operands load
// directly as u64 with no packing movs. B in padded-chunk conflict-free
// layout as before. Double-buffered, compile-time KSPLIT/RELU, 2 CTAs/SM.
// BM=128, BN=128, 256 threads, TM=8, TN=8.
// ---------------------------------------------------------------------------
#define BSROW 160   // B: 16 chunks * 10 floats (8 data + 2 pad)
#define ASROW 256   // A: 128 rows duplicated

template<int KSPLIT, int RELU>
__global__ void __launch_bounds__(256, 2)
sgemm5_kernel(const float* __restrict__ A, const float* __restrict__ B,
              const float* __restrict__ bias, float* __restrict__ C,
              int M, int N, int K,
              float* __restrict__ part)
{
    __shared__ float As2[2][16][ASROW];   // duplicated A
    __shared__ float Bs [2][16][BSROW];

    const int tid = threadIdx.x;
    const int tx  = tid & 15;
    const int ty  = tid >> 4;
    const int bm  = blockIdx.y * 128;
    const int bn  = blockIdx.x * 128;

    // split-K tile range (uneven allowed)
    const int tiles = K >> 4;
    int nT, kBase;
    if (KSPLIT > 1) {
        int tpz = tiles / KSPLIT;
        int rem = tiles - tpz * KSPLIT;
        int z = blockIdx.z;
        int st = z * tpz + (z < rem ? z : rem);
        nT = tpz + (z < rem ? 1 : 0);
        kBase = st << 4;
    } else { nT = tiles; kBase = 0; }

    // A tile load mapping: 128 rows x 16 k, 8 floats / thread
    const int alr = tid >> 1;
    const int alk = (tid & 1) * 8;
    const float* Ap = A + (size_t)(bm + alr) * K + kBase + alk;
    // B tile load mapping: 128 n-rows x 16 k, 8 floats / thread
    const int blr = tid >> 1;
    const int blk = (tid & 1) * 8;
    const int boff = (blr >> 3) * 10 + (blr & 7);   // padded-chunk column
    const float* Bp = B + (size_t)(bn + blr) * K + kBase + blk;

    float4 ra0, ra1, rb0, rb1;

    // prologue: tile 0 -> buf 0
    ra0 = *(const float4*)Ap; ra1 = *(const float4*)(Ap + 4);
    rb0 = *(const float4*)Bp; rb1 = *(const float4*)(Bp + 4);
    Ap += 16; Bp += 16;
    {
        float av[8] = {ra0.x, ra0.y, ra0.z, ra0.w, ra1.x, ra1.y, ra1.z, ra1.w};
        #pragma unroll
        for (int m = 0; m < 8; m++)
            *(u64*)&As2[0][alk+m][2*alr] = pk2(av[m], av[m]);
    }
    Bs[0][blk+0][boff]=rb0.x; Bs[0][blk+1][boff]=rb0.y;
    Bs[0][blk+2][boff]=rb0.z; Bs[0][blk+3][boff]=rb0.w;
    Bs[0][blk+4][boff]=rb1.x; Bs[0][blk+5][boff]=rb1.y;
    Bs[0][blk+6][boff]=rb1.z; Bs[0][blk+7][boff]=rb1.w;
    __syncthreads();

    u64 acc[8][4];
    #pragma unroll
    for (int i = 0; i < 8; i++)
        #pragma unroll
        for (int j = 0; j < 4; j++) acc[i][j] = 0ull;

    int buf = 0;
    for (int tI = 0; tI < nT; tI++) {
        const bool hasNext = (tI + 1 < nT);
        if (hasNext) {
            ra0 = *(const float4*)Ap; ra1 = *(const float4*)(Ap + 4);
            rb0 = *(const float4*)Bp; rb1 = *(const float4*)(Bp + 4);
            Ap += 16; Bp += 16;
        }
        #pragma unroll
        for (int kk = 0; kk < 16; kk++) {
            u64 a2[8];
            const float* abase = &As2[buf][kk][ty*16];   // 64B aligned
            lds_v2b64(a2[0], a2[1], abase);
            lds_v2b64(a2[2], a2[3], abase + 4);
            lds_v2b64(a2[4], a2[5], abase + 8);
            lds_v2b64(a2[6], a2[7], abase + 12);
            u64 b2[4];
            const u64* bp2 = (const u64*)&Bs[buf][kk][tx*10];  // conflict-free
            #pragma unroll
            for (int j = 0; j < 4; j++) b2[j] = bp2[j];
            #pragma unroll
            for (int i = 0; i < 8; i++)
                #pragma unroll
                for (int j = 0; j < 4; j++) fma2(acc[i][j], a2[i], b2[j]);
        }
        if (hasNext) {
            const int nb = buf ^ 1;
            float av[8] = {ra0.x, ra0.y, ra0.z, ra0.w, ra1.x, ra1.y, ra1.z, ra1.w};
            #pragma unroll
            for (int m = 0; m < 8; m++)
                *(u64*)&As2[nb][alk+m][2*alr] = pk2(av[m], av[m]);
            Bs[nb][blk+0][boff]=rb0.x; Bs[nb][blk+1][boff]=rb0.y;
            Bs[nb][blk+2][boff]=rb0.z; Bs[nb][blk+3][boff]=rb0.w;
            Bs[nb][blk+4][boff]=rb1.x; Bs[nb][blk+5][boff]=rb1.y;
            Bs[nb][blk+6][boff]=rb1.z; Bs[nb][blk+7][boff]=rb1.w;
        }
        __syncthreads();
        buf ^= 1;
    }

    if (KSPLIT > 1) {
        float* Cp0 = part + (size_t)blockIdx.z * M * N;
        #pragma unroll
        for (int i = 0; i < 8; i++) {
            float* Cp = Cp0 + (size_t)(bm + ty*8 + i) * N + bn + tx*8;
            #pragma unroll
            for (int j = 0; j < 4; j += 2) {
                float2 v0 = upk2(acc[i][j]);
                float2 v1 = upk2(acc[i][j+1]);
                *(float4*)(Cp + j*2) = make_float4(v0.x, v0.y, v1.x, v1.y);
            }
        }
    } else {
        float bv[8];
        #pragma unroll
        for (int j = 0; j < 8; j++) bv[j] = bias[bn + tx*8 + j];
        #pragma unroll
        for (int i = 0; i < 8; i++) {
            float* Cp = C + (size_t)(bm + ty*8 + i) * N + bn + tx*8;
            #pragma unroll
            for (int j = 0; j < 4; j += 2) {
                float2 v0 = upk2(acc[i][j]);
                float2 v1 = upk2(acc[i][j+1]);
                float4 v;
                v.x = v0.x + bv[j*2+0]; v.y = v0.y + bv[j*2+1];
                v.z = v1.x + bv[j*2+2]; v.w = v1.y + bv[j*2+3];
                if (RELU) {
                    v.x = fmaxf(v.x, 0.f); v.y = fmaxf(v.y, 0.f);
                    v.z = fmaxf(v.z, 0.f); v.w = fmaxf(v.w, 0.f);
                }
                *(float4*)(Cp + j*2) = v;
            }
        }
    }
}

// split-K reduce: C = sum_z part[z] + bias   (S <= 3)
__global__ void splitk_reduce_kernel(const float* __restrict__ part,
                                     const float* __restrict__ bias,
                                     float* __restrict__ C, int MN, int N, int S)
{
    int idx = blockIdx.x * blockDim.x + threadIdx.x;
    if (idx >= MN) return;
    float s = bias[idx % N] + part[idx];
    if (S > 1) s += part[idx + MN];
    if (S > 2) s += part[idx + 2*MN];
    C[idx] = s;
}

// ---------------------------------------------------------------------------
// 3x3 SAME conv + relu with FFMA2. Tile 16(x) x 64(y), 8 oc per block,
// each thread: 4 pixels x 8 oc (pixel pairs packed f32x2).
// ---------------------------------------------------------------------------
template<int IC, int ICC, int HH, int WW>
__global__ void __launch_bounds__(256)
conv3x3_relu2_kernel(const float* __restrict__ in, const float* __restrict__ w,
                     const float* __restrict__ bias, float* __restrict__ out)
{
    __shared__ float  sIn[ICC][66][18];
    __shared__ float2 sW2[8][ICC][9];

    const int tx = threadIdx.x & 15;
    const int ty = threadIdx.x >> 4;
    const int tilesX = WW / 16;
    const int bx = (blockIdx.x % tilesX) * 16;
    const int by = (blockIdx.x / tilesX) * 64;
    const int b   = blockIdx.y >> 3;
    const int ocg = (blockIdx.y & 7) * 8;

    u64 a01[8], a23[8];
    #pragma unroll
    for (int oc = 0; oc < 8; oc++) { a01[oc] = 0ull; a23[oc] = 0ull; }

    for (int icc = 0; icc < IC; icc += ICC) {
        for (int i = threadIdx.x; i < ICC*66*18; i += 256) {
            int col = i % 18; int t = i / 18; int row = t % 66; int ic = t / 66;
            int gx = bx + col - 1, gy = by + row - 1;
            float v = 0.f;
            if (gx >= 0 && gx < WW && gy >= 0 && gy < HH)
                v = in[(((size_t)b*IC + icc + ic)*HH + gy)*WW + gx];
            sIn[ic][row][col] = v;
        }
        for (int i = threadIdx.x; i < 8*ICC*9; i += 256) {
            int kk = i % 9; int t = i / 9; int ic = t % ICC; int oc = t / ICC;
            float wv = w[((ocg + oc)*IC + icc + ic)*9 + kk];
            sW2[oc][ic][kk] = make_float2(wv, wv);
        }
        __syncthreads();

        #pragma unroll
        for (int ic = 0; ic < ICC; ic++) {
            #pragma unroll
            for (int ky = 0; ky < 3; ky++) {
                #pragma unroll
                for (int kx = 0; kx < 3; kx++) {
                    float iv0 = sIn[ic][ty      + ky][tx + kx];
                    float iv1 = sIn[ic][ty + 16 + ky][tx + kx];
                    float iv2 = sIn[ic][ty + 32 + ky][tx + kx];
                    float iv3 = sIn[ic][ty + 48 + ky][tx + kx];
                    u64 p01 = pk2(iv0, iv1);
                    u64 p23 = pk2(iv2, iv3);
                    #pragma unroll
                    for (int oc = 0; oc < 8; oc++) {
                        u64 wv = *(const u64*)&sW2[oc][ic][ky*3 + kx];
                        fma2(a01[oc], p01, wv);
                        fma2(a23[oc], p23, wv);
                    }
                }
            }
        }
        __syncthreads();
    }

    #pragma unroll
    for (int oc = 0; oc < 8; oc++) {
        float bv = bias[ocg + oc];
        float2 v01 = upk2(a01[oc]);
        float2 v23 = upk2(a23[oc]);
        size_t base = (((size_t)b*64 + ocg + oc)*HH + by + ty)*WW + bx + tx;
        out[base            ] = fmaxf(v01.x + bv, 0.f);
        out[base + 16ull*WW ] = fmaxf(v01.y + bv, 0.f);
        out[base + 32ull*WW ] = fmaxf(v23.x + bv, 0.f);
        out[base + 48ull*WW ] = fmaxf(v23.y + bv, 0.f);
    }
}

// ---------------------------------------------------------------------------
// MHA core: one block per (b, head). 64 tokens, dh=192. 512 threads.
// ---------------------------------------------------------------------------
#define QKV_STRIDE 193
#define SC_STRIDE  65
#define ATTN_SMEM  ((3*64*QKV_STRIDE + 64*SC_STRIDE) * (int)sizeof(float))

__global__ void attn_kernel(const float* __restrict__ qkv, float* __restrict__ out)
{
    extern __shared__ float sm[];
    float* sQ = sm;
    float* sK = sQ + 64*QKV_STRIDE;
    float* sV = sK + 64*QKV_STRIDE;
    float* sS = sV + 64*QKV_STRIDE;

    const int bh = blockIdx.x;
    const int b  = bh >> 2;
    const int h  = bh & 3;
    const int base = b * 64;
    const float scale = 0.07216878364870323f; // 1/sqrt(192)

    for (int i = threadIdx.x; i < 64*DH; i += 512) {
        int r = i / DH, c = i % DH;
        size_t off = (size_t)(base + r)*2304 + h*DH + c;
        sQ[r*QKV_STRIDE + c] = qkv[off];
        sK[r*QKV_STRIDE + c] = qkv[off + 768];
        sV[r*QKV_STRIDE + c] = qkv[off + 1536];
    }
    __syncthreads();

    for (int e = threadIdx.x; e < 64*64; e += 512) {
        int i = e >> 6, j = e & 63;
        const float* q = sQ + i*QKV_STRIDE;
        const float* k = sK + j*QKV_STRIDE;
        float s = 0.f;
        #pragma unroll 8
        for (int d = 0; d < DH; d++) s = fmaf(q[d], k[d], s);
        sS[i*SC_STRIDE + j] = s * scale;
    }
    __syncthreads();

    if (threadIdx.x < 64) {
        float* row = sS + threadIdx.x * SC_STRIDE;
        float mx = row[0];
        #pragma unroll 8
        for (int j = 1; j < 64; j++) mx = fmaxf(mx, row[j]);
        float sum = 0.f;
        #pragma unroll 8
        for (int j = 0; j < 64; j++) { float e = __expf(row[j] - mx); row[j] = e; sum += e; }
        float inv = 1.f / sum;
        #pragma unroll 8
        for (int j = 0; j < 64; j++) row[j] *= inv;
    }
    __syncthreads();

    for (int e = threadIdx.x; e < 64*DH; e += 512) {
        int i = e / DH, d = e % DH;
        const float* p = sS + i*SC_STRIDE;
        float s = 0.f;
        #pragma unroll 8
        for (int j = 0; j < 64; j++) s = fmaf(p[j], sV[j*QKV_STRIDE + d], s);
        out[(size_t)(base + i)*EMB + h*DH + d] = s;
    }
}

// ---------------------------------------------------------------------------
// 2x2 maxpool (32,64,128,128) -> (32,64,64,64)
// ---------------------------------------------------------------------------
__global__ void maxpool_kernel(const float* __restrict__ in, float* __restrict__ out)
{
    int idx = blockIdx.x * blockDim.x + threadIdx.x;
    if (idx >= ROWS * HW2) return;
    int ox = idx & 63;
    int oy = (idx >> 6) & 63;
    int cb = idx >> 12;
    const float* p = in + ((size_t)cb*128 + oy*2)*128 + ox*2;
    out[idx] = fmaxf(fmaxf(p[0], p[1]), fmaxf(p[128], p[129]));
}

// ---------------------------------------------------------------------------
// fc2: (2048,2048) @ (4,2048)^T + bias -> (2048,4). One warp per row.
// ---------------------------------------------------------------------------
__global__ void fc2_kernel(const float* __restrict__ h1, const float* __restrict__ w,
                           const float* __restrict__ bias, float* __restrict__ tp)
{
    int warp = (blockIdx.x * blockDim.x + threadIdx.x) >> 5;
    int lane = threadIdx.x & 31;
    if (warp >= ROWS) return;
    const float* row = h1 + (size_t)warp * HC2;
    float a0 = 0.f, a1 = 0.f, a2 = 0.f, a3 = 0.f;
    for (int k = lane; k < HC2; k += 32) {
        float hv = row[k];
        a0 = fmaf(hv, w[k],          a0);
        a1 = fmaf(hv, w[HC2   + k],  a1);
        a2 = fmaf(hv, w[2*HC2 + k],  a2);
        a3 = fmaf(hv, w[3*HC2 + k],  a3);
    }
    #pragma unroll
    for (int o = 16; o > 0; o >>= 1) {
        a0 += __shfl_xor_sync(0xffffffffu, a0, o);
        a1 += __shfl_xor_sync(0xffffffffu, a1, o);
        a2 += __shfl_xor_sync(0xffffffffu, a2, o);
        a3 += __shfl_xor_sync(0xffffffffu, a3, o);
    }
    if (lane == 0) {
        tp[warp*4 + 0] = a0 + bias[0];
        tp[warp*4 + 1] = a1 + bias[1];
        tp[warp*4 + 2] = a2 + bias[2];
        tp[warp*4 + 3] = a3 + bias[3];
    }
}

// ---------------------------------------------------------------------------
// Affine params + translate output
// ---------------------------------------------------------------------------
__global__ void params_kernel(const float* __restrict__ tp, float* __restrict__ par,
                              float* __restrict__ out_translate)
{
    int i = blockIdx.x * blockDim.x + threadIdx.x;
    if (i >= ROWS) return;
    float t0 = tp[i*4+0], t1 = tp[i*4+1], t2 = tp[i*4+2], t3 = tp[i*4+3];
    float trx = tanhf(t0);
    float trY = tanhf(t1);
    float s   = 0.3f / (1.f + expf(-t2));
    float rot = tanhf(t3) * 3.14159265358979323846f;
    float sn, cs;
    sincosf(rot, &sn, &cs);
    float x_ext = fminf(s*fabsf(cs) + s*fabsf(sn), 1.f);
    float y_ext = fminf(s*fabsf(sn) + s*fabsf(cs), 1.f);
    float txv = trx * (1.f - x_ext);
    float tyv = trY * (1.f - y_ext);
    par[i*6+0] =  s*cs;
    par[i*6+1] = -s*sn;
    par[i*6+2] =  s*sn;
    par[i*6+3] =  s*cs;
    par[i*6+4] =  txv;
    par[i*6+5] =  tyv;
    out_translate[i*2+0] = txv;
    out_translate[i*2+1] = tyv;
}

// ---------------------------------------------------------------------------
// Bilinear grid sample -> patches (B*NP, C, P, P)
// ---------------------------------------------------------------------------
__global__ void gridsample_kernel(const float* __restrict__ x,
                                  const float* __restrict__ par,
                                  float* __restrict__ out)
{
    int idx = blockIdx.x * blockDim.x + threadIdx.x;
    const int total = ROWS * CIN * PSZ * PSZ;
    if (idx >= total) return;
    int px = idx & 15;
    int py = (idx >> 4) & 15;
    int c  = (idx >> 8) % 3;
    int bp = idx / (3*256);
    int b  = bp >> 6;

    float ta = par[bp*6+0], tb = par[bp*6+1], tc = par[bp*6+2];
    float td = par[bp*6+3], txp = par[bp*6+4], typ = par[bp*6+5];

    float bxv = (2.f*px + 1.f) / 16.f - 1.f;
    float byv = (2.f*py + 1.f) / 16.f - 1.f;
    float gx = ta*bxv + tb*byv + txp;
    float gy = tc*bxv + td*byv + typ;

    float xs = ((gx + 1.f) * (float)WIMG - 1.f) * 0.5f;
    float ys = ((gy + 1.f) * (float)HIMG - 1.f) * 0.5f;
    float x0f = floorf(xs), y0f = floorf(ys);
    float wx = xs - x0f, wy = ys - y0f;
    int x0 = (int)x0f, y0 = (int)y0f;

    const float* img = x + ((size_t)b*3 + c) * (HIMG*WIMG);
    float v00 = 0.f, v01 = 0.f, v10 = 0.f, v11 = 0.f;
    bool xv0 = (x0   >= 0) & (x0   < WIMG);
    bool xv1 = (x0+1 >= 0) & (x0+1 < WIMG);
    bool yv0 = (y0   >= 0) & (y0   < HIMG);
    bool yv1 = (y0+1 >= 0) & (y0+1 < HIMG);
    if (yv0 & xv0) v00 = img[y0*WIMG + x0];
    if (yv0 & xv1) v01 = img[y0*WIMG + x0 + 1];
    if (yv1 & xv0) v10 = img[(y0+1)*WIMG + x0];
    if (yv1 & xv1) v11 = img[(y0+1)*WIMG + x0 + 1];

    out[idx] = v00*(1.f-wx)*(1.f-wy) + v01*wx*(1.f-wy)
             + v10*(1.f-wx)*wy       + v11*wx*wy;
}

// ---------------------------------------------------------------------------
// kernel_launch
// ---------------------------------------------------------------------------
extern "C" void kernel_launch(void* const* d_in, const int* in_sizes, int n_in,
                              void* d_out, int out_size)
{
    const float* x        = (const float*)d_in[0];
    const float* conv1_w  = (const float*)d_in[1];
    const float* conv1_b  = (const float*)d_in[2];
    const float* a1_in_w  = (const float*)d_in[3];
    const float* a1_in_b  = (const float*)d_in[4];
    const float* a1_qkv_w = (const float*)d_in[5];
    const float* a1_qkv_b = (const float*)d_in[6];
    const float* a1_out_w = (const float*)d_in[7];
    const float* a1_out_b = (const float*)d_in[8];
    const float* a1_proj_w= (const float*)d_in[9];
    const float* a1_proj_b= (const float*)d_in[10];
    const float* conv2_w  = (const float*)d_in[11];
    const float* conv2_b  = (const float*)d_in[12];
    const float* a2_in_w  = (const float*)d_in[13];
    const float* a2_in_b  = (const float*)d_in[14];
    const float* a2_qkv_w = (const float*)d_in[15];
    const float* a2_qkv_b = (const float*)d_in[16];
    const float* a2_out_w = (const float*)d_in[17];
    const float* a2_out_b = (const float*)d_in[18];
    const float* a2_proj_w= (const float*)d_in[19];
    const float* a2_proj_b= (const float*)d_in[20];
    const float* fc1_w    = (const float*)d_in[21];
    const float* fc1_b    = (const float*)d_in[22];
    const float* fc2_w    = (const float*)d_in[23];
    const float* fc2_b    = (const float*)d_in[24];

    float* out = (float*)d_out;
    float* out_patches   = out;
    float* out_translate = out + ROWS*CIN*PSZ*PSZ;

    float *f1, *y1, *pool, *f2, *y2, *t, *qkv, *att, *o, *h1, *tp, *par, *part;
    cudaGetSymbolAddress((void**)&f1,   g_f1);
    cudaGetSymbolAddress((void**)&y1,   g_y1);
    cudaGetSymbolAddress((void**)&pool, g_pool);
    cudaGetSymbolAddress((void**)&f2,   g_f2);
    cudaGetSymbolAddress((void**)&y2,   g_y2);
    cudaGetSymbolAddress((void**)&t,    g_t);
    cudaGetSymbolAddress((void**)&qkv,  g_qkv);
    cudaGetSymbolAddress((void**)&att,  g_att);
    cudaGetSymbolAddress((void**)&o,    g_o);
    cudaGetSymbolAddress((void**)&h1,   g_h1);
    cudaGetSymbolAddress((void**)&tp,   g_tp);
    cudaGetSymbolAddress((void**)&par,  g_par);
    cudaGetSymbolAddress((void**)&part, g_part);

    cudaFuncSetAttribute(attn_kernel,
                         cudaFuncAttributeMaxDynamicSharedMemorySize, ATTN_SMEM);

    const int MN768 = ROWS * EMB;

    // --- conv1 + relu (32,3,128,128) -> (32,64,128,128)
    conv3x3_relu2_kernel<3, 3, 128, 128>
        <<<dim3((128/16)*(128/64), BATCH*8), 256>>>(x, conv1_w, conv1_b, f1);

    // --- attention block 1
    // a1_in: 2048x768, K=16384, split-K=3 -> 288 blocks
    sgemm5_kernel<3,0><<<dim3(6, 16, 3), 256>>>(f1, a1_in_w, nullptr, nullptr,
                                                ROWS, EMB, HW1, part);
    splitk_reduce_kernel<<<(MN768 + 255)/256, 256>>>(part, a1_in_b, t, MN768, EMB, 3);
    // qkv: 2048x2304, K=768 -> 288 blocks
    sgemm5_kernel<1,0><<<dim3(18, 16, 1), 256>>>(t, a1_qkv_w, a1_qkv_b, qkv,
                                                 ROWS, 3*EMB, EMB, nullptr);
    attn_kernel<<<BATCH*4, 512, ATTN_SMEM>>>(qkv, att);
    // out: 2048x768, K=768, split-K=3
    sgemm5_kernel<3,0><<<dim3(6, 16, 3), 256>>>(att, a1_out_w, nullptr, nullptr,
                                                ROWS, EMB, EMB, part);
    splitk_reduce_kernel<<<(MN768 + 255)/256, 256>>>(part, a1_out_b, o, MN768, EMB, 3);
    // proj1: 2048x16384, K=768 -> 2048 blocks
    sgemm5_kernel<1,0><<<dim3(128, 16, 1), 256>>>(o, a1_proj_w, a1_proj_b, y1,
                                                  ROWS, HW1, EMB, nullptr);

    // --- maxpool
    maxpool_kernel<<<(ROWS*HW2 + 255)/256, 256>>>(y1, pool);

    // --- conv2 + relu (32,64,64,64) -> (32,64,64,64)
    conv3x3_relu2_kernel<64, 8, 64, 64>
        <<<dim3((64/16)*(64/64), BATCH*8), 256>>>(pool, conv2_w, conv2_b, f2);

    // --- attention block 2
    sgemm5_kernel<3,0><<<dim3(6, 16, 3), 256>>>(f2, a2_in_w, nullptr, nullptr,
                                                ROWS, EMB, HW2, part);
    splitk_reduce_kernel<<<(MN768 + 255)/256, 256>>>(part, a2_in_b, t, MN768, EMB, 3);
    sgemm5_kernel<1,0><<<dim3(18, 16, 1), 256>>>(t, a2_qkv_w, a2_qkv_b, qkv,
                                                 ROWS, 3*EMB, EMB, nullptr);
    attn_kernel<<<BATCH*4, 512, ATTN_SMEM>>>(qkv, att);
    sgemm5_kernel<3,0><<<dim3(6, 16, 3), 256>>>(att, a2_out_w, nullptr, nullptr,
                                                ROWS, EMB, EMB, part);
    splitk_reduce_kernel<<<(MN768 + 255)/256, 256>>>(part, a2_out_b, o, MN768, EMB, 3);
    // proj2: 2048x4096, K=768 -> 512 blocks
    sgemm5_kernel<1,0><<<dim3(32, 16, 1), 256>>>(o, a2_proj_w, a2_proj_b, y2,
                                                 ROWS, HW2, EMB, nullptr);

    // --- head
    // fc1: 2048x2048, K=4096 -> 256 blocks, fused relu
    sgemm5_kernel<1,1><<<dim3(16, 16, 1), 256>>>(y2, fc1_w, fc1_b, h1,
                                                 ROWS, HC2, HW2, nullptr);
    fc2_kernel<<<(ROWS*32 + 255)/256, 256>>>(h1, fc2_w, fc2_b, tp);
    params_kernel<<<(ROWS + 255)/256, 256>>>(tp, par, out_translate);
    gridsample_kernel<<<(ROWS*CIN*PSZ*PSZ + 255)/256, 256>>>(x, par, out_patches);
}

// round 12
// speedup vs baseline: 2.2626x; 2.2626x over previous
#include <cuda_runtime.h>
#include <cuda_bf16.h>
#include <cstdint>
#include <math.h>

// ---------------------------------------------------------------------------
// Problem constants
// ---------------------------------------------------------------------------
#define BATCH 32
#define CIN   3
#define HIMG  128
#define WIMG  128
#define PSZ   16
#define EMB   768
#define DH    192
#define ROWS  2048         // BATCH * 64
#define HW1   16384
#define HW2   4096
#define HC2   2048

typedef unsigned long long u64;

// ---------------------------------------------------------------------------
// helpers
// ---------------------------------------------------------------------------
__device__ __forceinline__ uint32_t smem_to_u32(const void* p) {
    uint32_t a;
    asm("{ .reg .u64 t; cvta.to.shared.u64 t, %1; cvt.u32.u64 %0, t; }"
        : "=r"(a) : "l"(p));
    return a;
}

#define CP_ASYNC16(saddr, gptr) \
    asm volatile("cp.async.cg.shared.global [%0], [%1], 16;" \
        :: "r"(saddr), "l"(gptr) : "memory")
#define CP_COMMIT() asm volatile("cp.async.commit_group;" ::: "memory")
#define CP_WAIT1()  asm volatile("cp.async.wait_group 1;" ::: "memory")
#define CP_WAIT0()  asm volatile("cp.async.wait_group 0;" ::: "memory")

__device__ __forceinline__ void ldsm4(uint32_t* r, uint32_t saddr) {
    asm volatile("ldmatrix.sync.aligned.m8n8.x4.shared.b16 {%0,%1,%2,%3}, [%4];"
        : "=r"(r[0]), "=r"(r[1]), "=r"(r[2]), "=r"(r[3]) : "r"(saddr));
}
__device__ __forceinline__ void mma_bf16(float* d, const uint32_t* a, const uint32_t* b) {
    asm volatile("mma.sync.aligned.m16n8k16.row.col.f32.bf16.bf16.f32 "
        "{%0,%1,%2,%3},{%4,%5,%6,%7},{%8,%9},{%0,%1,%2,%3};"
        : "+f"(d[0]), "+f"(d[1]), "+f"(d[2]), "+f"(d[3])
        : "r"(a[0]), "r"(a[1]), "r"(a[2]), "r"(a[3]), "r"(b[0]), "r"(b[1]));
}

// f32x2 helpers (FFMA2 for the convs)
__device__ __forceinline__ u64 pk2(float lo, float hi) {
    u64 r; asm("mov.b64 %0, {%1,%2};" : "=l"(r) : "f"(lo), "f"(hi)); return r;
}
__device__ __forceinline__ void fma2(u64& d, u64 a, u64 b) {
    asm("fma.rn.f32x2 %0, %1, %2, %0;" : "+l"(d) : "l"(a), "l"(b));
}
__device__ __forceinline__ float2 upk2(u64 v) {
    float2 f; asm("mov.b64 {%0,%1}, %2;" : "=f"(f.x), "=f"(f.y) : "l"(v)); return f;
}

// ---------------------------------------------------------------------------
// Scratch (device globals; no runtime allocation allowed)
// ---------------------------------------------------------------------------
__device__ float g_f1  [ROWS * HW1];
__device__ float g_y1  [ROWS * HW1];
__device__ float g_pool[ROWS * HW2];
__device__ float g_f2  [ROWS * HW2];
__device__ float g_y2  [ROWS * HW2];
__device__ float g_t   [ROWS * EMB];
__device__ float g_qkv [ROWS * 3 * EMB];
__device__ float g_att [ROWS * EMB];
__device__ float g_o   [ROWS * EMB];
__device__ float g_h1  [ROWS * HC2];
__device__ float g_tp  [ROWS * 4];
__device__ float g_par [ROWS * 6];
__device__ float g_part[3 * ROWS * EMB];            // split-K partials
__device__ __nv_bfloat16 g_Ah[ROWS * HW1];          // A hi
__device__ __nv_bfloat16 g_Al[ROWS * HW1];          // A lo
__device__ __nv_bfloat16 g_Bh[HW1 * EMB];           // B hi
__device__ __nv_bfloat16 g_Bl[HW1 * EMB];           // B lo

// ---------------------------------------------------------------------------
// fp32 -> (bf16 hi, bf16 lo) split conversion, vectorized x4
// ---------------------------------------------------------------------------
__global__ void cvt_split_kernel(const float* __restrict__ s,
                                 __nv_bfloat16* __restrict__ hi,
                                 __nv_bfloat16* __restrict__ lo, int n4)
{
    int i = blockIdx.x * blockDim.x + threadIdx.x;
    if (i >= n4) return;
    float4 v = ((const float4*)s)[i];
    __nv_bfloat16 h0 = __float2bfloat16(v.x);
    __nv_bfloat16 h1 = __float2bfloat16(v.y);
    __nv_bfloat16 h2 = __float2bfloat16(v.z);
    __nv_bfloat16 h3 = __float2bfloat16(v.w);
    __nv_bfloat16 l0 = __float2bfloat16(v.x - __bfloat162float(h0));
    __nv_bfloat16 l1 = __float2bfloat16(v.y - __bfloat162float(h1));
    __nv_bfloat16 l2 = __float2bfloat16(v.z - __bfloat162float(h2));
    __nv_bfloat16 l3 = __float2bfloat16(v.w - __bfloat162float(h3));
    ((__nv_bfloat162*)hi)[2*i  ] = __nv_bfloat162(h0, h1);
    ((__nv_bfloat162*)hi)[2*i+1] = __nv_bfloat162(h2, h3);
    ((__nv_bfloat162*)lo)[2*i  ] = __nv_bfloat162(l0, l1);
    ((__nv_bfloat162*)lo)[2*i+1] = __nv_bfloat162(l2, l3);
}

// ---------------------------------------------------------------------------
// Tensor-core GEMM via mma.sync m16n8k16 bf16, 3-split (Ah*Bh + Ah*Bl + Al*Bh).
// C[M,N] = A[M,K] @ B[N,K]^T (+bias,+relu). BM=128, BN=128, BK=32.
// 256 thr = 8 warps (2m x 4n), warp tile 64x32. cp.async double buffering.
// smem rows padded to 40 bf16 (80B) -> conflict-free ldmatrix.
// ---------------------------------------------------------------------------
#define TROW   40                    // bf16 per smem row (32 data + 8 pad)
#define TBYTES (128 * TROW * 2)      // one 128x32 tile = 10240 B
// tile buffer byte offset: matrix m (0=Ah,1=Al,2=Bh,3=Bl), buffer b
#define TOFF(m, b) ((uint32_t)(((m) * 2 + (b)) * TBYTES))
#define GMM_SMEM (8 * TBYTES)        // 81920 B

template<int KSPLIT, int RELU>
__global__ void __launch_bounds__(256, 2)
gemm_mma_kernel(const __nv_bfloat16* __restrict__ Ah, const __nv_bfloat16* __restrict__ Al,
                const __nv_bfloat16* __restrict__ Bh, const __nv_bfloat16* __restrict__ Bl,
                const float* __restrict__ bias, float* __restrict__ C,
                int M, int N, int K, float* __restrict__ part)
{
    extern __shared__ __align__(16) char smbuf[];
    const uint32_t sb = smem_to_u32(smbuf);
    const int tid  = threadIdx.x;
    const int lane = tid & 31;
    const int wid  = tid >> 5;
    const int wm   = (wid >> 2) * 64;   // 0 / 64
    const int wn   = (wid & 3) * 32;    // 0 / 32 / 64 / 96
    const int bm   = blockIdx.y * 128;
    const int bn   = blockIdx.x * 128;

    // k-tile range (BK=32 per tile), uneven split allowed
    const int tiles = K >> 5;
    int t0 = 0, t1 = tiles;
    if (KSPLIT > 1) {
        int per = tiles / KSPLIT, rem = tiles - per * KSPLIT;
        int z = blockIdx.z;
        t0 = z * per + (z < rem ? z : rem);
        t1 = t0 + per + (z < rem ? 1 : 0);
    }

    // loader lane mapping: v = tid + half*256 -> row = v>>2, cv = v&3
    const int lrow0 = tid >> 2, lcv0 = tid & 3;
    const int lrow1 = (tid + 256) >> 2, lcv1 = (tid + 256) & 3;

    // ldmatrix lane offsets
    const int a_row = lane & 15;
    const int a_colb = ((lane >> 4) * 8) * 2;              // byte offset in row
    const int b_row = ((lane >> 4) & 1) * 8 + (lane & 7);
    const int b_colb = (((lane >> 3) & 1) * 8) * 2;

    float d[4][4][4];
    #pragma unroll
    for (int i = 0; i < 4; i++)
        #pragma unroll
        for (int j = 0; j < 4; j++)
            #pragma unroll
            for (int q = 0; q < 4; q++) d[i][j][q] = 0.f;

    // ---- issue loads for tile t0 into buffer 0
    {
        const int kb = t0 << 5;
        uint32_t s0 = (uint32_t)(lrow0 * 80 + lcv0 * 16);
        uint32_t s1 = (uint32_t)(lrow1 * 80 + lcv1 * 16);
        size_t ga0 = (size_t)(bm + lrow0) * K + kb + lcv0 * 8;
        size_t ga1 = (size_t)(bm + lrow1) * K + kb + lcv1 * 8;
        size_t gb0 = (size_t)(bn + lrow0) * K + kb + lcv0 * 8;
        size_t gb1 = (size_t)(bn + lrow1) * K + kb + lcv1 * 8;
        CP_ASYNC16(sb + TOFF(0,0) + s0, Ah + ga0);
        CP_ASYNC16(sb + TOFF(0,0) + s1, Ah + ga1);
        CP_ASYNC16(sb + TOFF(1,0) + s0, Al + ga0);
        CP_ASYNC16(sb + TOFF(1,0) + s1, Al + ga1);
        CP_ASYNC16(sb + TOFF(2,0) + s0, Bh + gb0);
        CP_ASYNC16(sb + TOFF(2,0) + s1, Bh + gb1);
        CP_ASYNC16(sb + TOFF(3,0) + s0, Bl + gb0);
        CP_ASYNC16(sb + TOFF(3,0) + s1, Bl + gb1);
        CP_COMMIT();
    }

    int buf = 0;
    for (int t = t0; t < t1; t++) {
        const bool hasNext = (t + 1 < t1);
        if (hasNext) {
            const int kb = (t + 1) << 5;
            const int nb = buf ^ 1;
            uint32_t s0 = (uint32_t)(lrow0 * 80 + lcv0 * 16);
            uint32_t s1 = (uint32_t)(lrow1 * 80 + lcv1 * 16);
            size_t ga0 = (size_t)(bm + lrow0) * K + kb + lcv0 * 8;
            size_t ga1 = (size_t)(bm + lrow1) * K + kb + lcv1 * 8;
            size_t gb0 = (size_t)(bn + lrow0) * K + kb + lcv0 * 8;
            size_t gb1 = (size_t)(bn + lrow1) * K + kb + lcv1 * 8;
            CP_ASYNC16(sb + TOFF(0,nb) + s0, Ah + ga0);
            CP_ASYNC16(sb + TOFF(0,nb) + s1, Ah + ga1);
            CP_ASYNC16(sb + TOFF(1,nb) + s0, Al + ga0);
            CP_ASYNC16(sb + TOFF(1,nb) + s1, Al + ga1);
            CP_ASYNC16(sb + TOFF(2,nb) + s0, Bh + gb0);
            CP_ASYNC16(sb + TOFF(2,nb) + s1, Bh + gb1);
            CP_ASYNC16(sb + TOFF(3,nb) + s0, Bl + gb0);
            CP_ASYNC16(sb + TOFF(3,nb) + s1, Bl + gb1);
            CP_COMMIT();
            CP_WAIT1();
        } else {
            CP_WAIT0();
        }
        __syncthreads();

        #pragma unroll
        for (int s = 0; s < 2; s++) {
            const uint32_t scolb = (uint32_t)(s * 32);   // s*16 bf16 = 32 B
            uint32_t ah[4][4], bh[2][4], bl[2][4];
            #pragma unroll
            for (int mt = 0; mt < 4; mt++)
                ldsm4(ah[mt], sb + TOFF(0,buf)
                      + (uint32_t)((wm + mt*16 + a_row) * 80) + scolb + a_colb);
            #pragma unroll
            for (int np = 0; np < 2; np++)
                ldsm4(bh[np], sb + TOFF(2,buf)
                      + (uint32_t)((wn + np*16 + b_row) * 80) + scolb + b_colb);
            #pragma unroll
            for (int np = 0; np < 2; np++)
                ldsm4(bl[np], sb + TOFF(3,buf)
                      + (uint32_t)((wn + np*16 + b_row) * 80) + scolb + b_colb);
            // Ah * Bh
            #pragma unroll
            for (int mt = 0; mt < 4; mt++)
                #pragma unroll
                for (int nt = 0; nt < 4; nt++)
                    mma_bf16(d[mt][nt], ah[mt], &bh[nt>>1][(nt&1)*2]);
            // Ah * Bl
            #pragma unroll
            for (int mt = 0; mt < 4; mt++)
                #pragma unroll
                for (int nt = 0; nt < 4; nt++)
                    mma_bf16(d[mt][nt], ah[mt], &bl[nt>>1][(nt&1)*2]);
            // Al * Bh (reuse ah regs)
            #pragma unroll
            for (int mt = 0; mt < 4; mt++)
                ldsm4(ah[mt], sb + TOFF(1,buf)
                      + (uint32_t)((wm + mt*16 + a_row) * 80) + scolb + a_colb);
            #pragma unroll
            for (int mt = 0; mt < 4; mt++)
                #pragma unroll
                for (int nt = 0; nt < 4; nt++)
                    mma_bf16(d[mt][nt], ah[mt], &bh[nt>>1][(nt&1)*2]);
        }
        __syncthreads();
        buf ^= 1;
    }

    // ---- epilogue
    const int er = lane >> 2;          // 0..7
    const int ec = (lane & 3) * 2;     // 0,2,4,6
    if (KSPLIT > 1) {
        float* P = part + (size_t)blockIdx.z * M * N;
        #pragma unroll
        for (int mt = 0; mt < 4; mt++) {
            #pragma unroll
            for (int nt = 0; nt < 4; nt++) {
                int r = bm + wm + mt*16 + er;
                int c = bn + wn + nt*8 + ec;
                *(float2*)(P + (size_t)r * N + c)       = make_float2(d[mt][nt][0], d[mt][nt][1]);
                *(float2*)(P + (size_t)(r + 8) * N + c) = make_float2(d[mt][nt][2], d[mt][nt][3]);
            }
        }
    } else {
        #pragma unroll
        for (int mt = 0; mt < 4; mt++) {
            #pragma unroll
            for (int nt = 0; nt < 4; nt++) {
                int r = bm + wm + mt*16 + er;
                int c = bn + wn + nt*8 + ec;
                float b0 = bias[c], b1 = bias[c+1];
                float v0 = d[mt][nt][0] + b0, v1 = d[mt][nt][1] + b1;
                float v2 = d[mt][nt][2] + b0, v3 = d[mt][nt][3] + b1;
                if (RELU) {
                    v0 = fmaxf(v0, 0.f); v1 = fmaxf(v1, 0.f);
                    v2 = fmaxf(v2, 0.f); v3 = fmaxf(v3, 0.f);
                }
                *(float2*)(C + (size_t)r * N + c)       = make_float2(v0, v1);
                *(float2*)(C + (size_t)(r + 8) * N + c) = make_float2(v2, v3);
            }
        }
    }
}

// split-K reduce: C = sum_z part[z] + bias   (S <= 3)
__global__ void splitk_reduce_kernel(const float* __restrict__ part,
                                     const float* __restrict__ bias,
                                     float* __restrict__ C, int MN, int N, int S)
{
    int idx = blockIdx.x * blockDim.x + threadIdx.x;
    if (idx >= MN) return;
    float s = bias[idx % N] + part[idx];
    if (S > 1) s += part[idx + MN];
    if (S > 2) s += part[idx + 2*MN];
    C[idx] = s;
}

// ---------------------------------------------------------------------------
// 3x3 SAME conv + relu with FFMA2 (unchanged from round 7)
// ---------------------------------------------------------------------------
template<int IC, int ICC, int HH, int WW>
__global__ void __launch_bounds__(256)
conv3x3_relu2_kernel(const float* __restrict__ in, const float* __restrict__ w,
                     const float* __restrict__ bias, float* __restrict__ out)
{
    __shared__ float  sIn[ICC][66][18];
    __shared__ float2 sW2[8][ICC][9];

    const int tx = threadIdx.x & 15;
    const int ty = threadIdx.x >> 4;
    const int tilesX = WW / 16;
    const int bx = (blockIdx.x % tilesX) * 16;
    const int by = (blockIdx.x / tilesX) * 64;
    const int b   = blockIdx.y >> 3;
    const int ocg = (blockIdx.y & 7) * 8;

    u64 a01[8], a23[8];
    #pragma unroll
    for (int oc = 0; oc < 8; oc++) { a01[oc] = 0ull; a23[oc] = 0ull; }

    for (int icc = 0; icc < IC; icc += ICC) {
        for (int i = threadIdx.x; i < ICC*66*18; i += 256) {
            int col = i % 18; int t = i / 18; int row = t % 66; int ic = t / 66;
            int gx = bx + col - 1, gy = by + row - 1;
            float v = 0.f;
            if (gx >= 0 && gx < WW && gy >= 0 && gy < HH)
                v = in[(((size_t)b*IC + icc + ic)*HH + gy)*WW + gx];
            sIn[ic][row][col] = v;
        }
        for (int i = threadIdx.x; i < 8*ICC*9; i += 256) {
            int kk = i % 9; int t = i / 9; int ic = t % ICC; int oc = t / ICC;
            float wv = w[((ocg + oc)*IC + icc + ic)*9 + kk];
            sW2[oc][ic][kk] = make_float2(wv, wv);
        }
        __syncthreads();

        #pragma unroll
        for (int ic = 0; ic < ICC; ic++) {
            #pragma unroll
            for (int ky = 0; ky < 3; ky++) {
                #pragma unroll
                for (int kx = 0; kx < 3; kx++) {
                    float iv0 = sIn[ic][ty      + ky][tx + kx];
                    float iv1 = sIn[ic][ty + 16 + ky][tx + kx];
                    float iv2 = sIn[ic][ty + 32 + ky][tx + kx];
                    float iv3 = sIn[ic][ty + 48 + ky][tx + kx];
                    u64 p01 = pk2(iv0, iv1);
                    u64 p23 = pk2(iv2, iv3);
                    #pragma unroll
                    for (int oc = 0; oc < 8; oc++) {
                        u64 wv = *(const u64*)&sW2[oc][ic][ky*3 + kx];
                        fma2(a01[oc], p01, wv);
                        fma2(a23[oc], p23, wv);
                    }
                }
            }
        }
        __syncthreads();
    }

    #pragma unroll
    for (int oc = 0; oc < 8; oc++) {
        float bv = bias[ocg + oc];
        float2 v01 = upk2(a01[oc]);
        float2 v23 = upk2(a23[oc]);
        size_t base = (((size_t)b*64 + ocg + oc)*HH + by + ty)*WW + bx + tx;
        out[base            ] = fmaxf(v01.x + bv, 0.f);
        out[base + 16ull*WW ] = fmaxf(v01.y + bv, 0.f);
        out[base + 32ull*WW ] = fmaxf(v23.x + bv, 0.f);
        out[base + 48ull*WW ] = fmaxf(v23.y + bv, 0.f);
    }
}

// ---------------------------------------------------------------------------
// MHA core (unchanged)
// ---------------------------------------------------------------------------
#define QKV_STRIDE 193
#define SC_STRIDE  65
#define ATTN_SMEM  ((3*64*QKV_STRIDE + 64*SC_STRIDE) * (int)sizeof(float))

__global__ void attn_kernel(const float* __restrict__ qkv, float* __restrict__ out)
{
    extern __shared__ float sm[];
    float* sQ = sm;
    float* sK = sQ + 64*QKV_STRIDE;
    float* sV = sK + 64*QKV_STRIDE;
    float* sS = sV + 64*QKV_STRIDE;

    const int bh = blockIdx.x;
    const int b  = bh >> 2;
    const int h  = bh & 3;
    const int base = b * 64;
    const float scale = 0.07216878364870323f; // 1/sqrt(192)

    for (int i = threadIdx.x; i < 64*DH; i += 512) {
        int r = i / DH, c = i % DH;
        size_t off = (size_t)(base + r)*2304 + h*DH + c;
        sQ[r*QKV_STRIDE + c] = qkv[off];
        sK[r*QKV_STRIDE + c] = qkv[off + 768];
        sV[r*QKV_STRIDE + c] = qkv[off + 1536];
    }
    __syncthreads();

    for (int e = threadIdx.x; e < 64*64; e += 512) {
        int i = e >> 6, j = e & 63;
        const float* q = sQ + i*QKV_STRIDE;
        const float* k = sK + j*QKV_STRIDE;
        float s = 0.f;
        #pragma unroll 8
        for (int d = 0; d < DH; d++) s = fmaf(q[d], k[d], s);
        sS[i*SC_STRIDE + j] = s * scale;
    }
    __syncthreads();

    if (threadIdx.x < 64) {
        float* row = sS + threadIdx.x * SC_STRIDE;
        float mx = row[0];
        #pragma unroll 8
        for (int j = 1; j < 64; j++) mx = fmaxf(mx, row[j]);
        float sum = 0.f;
        #pragma unroll 8
        for (int j = 0; j < 64; j++) { float e = __expf(row[j] - mx); row[j] = e; sum += e; }
        float inv = 1.f / sum;
        #pragma unroll 8
        for (int j = 0; j < 64; j++) row[j] *= inv;
    }
    __syncthreads();

    for (int e = threadIdx.x; e < 64*DH; e += 512) {
        int i = e / DH, d = e % DH;
        const float* p = sS + i*SC_STRIDE;
        float s = 0.f;
        #pragma unroll 8
        for (int j = 0; j < 64; j++) s = fmaf(p[j], sV[j*QKV_STRIDE + d], s);
        out[(size_t)(base + i)*EMB + h*DH + d] = s;
    }
}

// ---------------------------------------------------------------------------
// 2x2 maxpool, fc2, params, gridsample (unchanged)
// ---------------------------------------------------------------------------
__global__ void maxpool_kernel(const float* __restrict__ in, float* __restrict__ out)
{
    int idx = blockIdx.x * blockDim.x + threadIdx.x;
    if (idx >= ROWS * HW2) return;
    int ox = idx & 63;
    int oy = (idx >> 6) & 63;
    int cb = idx >> 12;
    const float* p = in + ((size_t)cb*128 + oy*2)*128 + ox*2;
    out[idx] = fmaxf(fmaxf(p[0], p[1]), fmaxf(p[128], p[129]));
}

__global__ void fc2_kernel(const float* __restrict__ h1, const float* __restrict__ w,
                           const float* __restrict__ bias, float* __restrict__ tp)
{
    int warp = (blockIdx.x * blockDim.x + threadIdx.x) >> 5;
    int lane = threadIdx.x & 31;
    if (warp >= ROWS) return;
    const float* row = h1 + (size_t)warp * HC2;
    float a0 = 0.f, a1 = 0.f, a2 = 0.f, a3 = 0.f;
    for (int k = lane; k < HC2; k += 32) {
        float hv = row[k];
        a0 = fmaf(hv, w[k],          a0);
        a1 = fmaf(hv, w[HC2   + k],  a1);
        a2 = fmaf(hv, w[2*HC2 + k],  a2);
        a3 = fmaf(hv, w[3*HC2 + k],  a3);
    }
    #pragma unroll
    for (int o = 16; o > 0; o >>= 1) {
        a0 += __shfl_xor_sync(0xffffffffu, a0, o);
        a1 += __shfl_xor_sync(0xffffffffu, a1, o);
        a2 += __shfl_xor_sync(0xffffffffu, a2, o);
        a3 += __shfl_xor_sync(0xffffffffu, a3, o);
    }
    if (lane == 0) {
        tp[warp*4 + 0] = a0 + bias[0];
        tp[warp*4 + 1] = a1 + bias[1];
        tp[warp*4 + 2] = a2 + bias[2];
        tp[warp*4 + 3] = a3 + bias[3];
    }
}

__global__ void params_kernel(const float* __restrict__ tp, float* __restrict__ par,
                              float* __restrict__ out_translate)
{
    int i = blockIdx.x * blockDim.x + threadIdx.x;
    if (i >= ROWS) return;
    float t0 = tp[i*4+0], t1 = tp[i*4+1], t2 = tp[i*4+2], t3 = tp[i*4+3];
    float trx = tanhf(t0);
    float trY = tanhf(t1);
    float s   = 0.3f / (1.f + expf(-t2));
    float rot = tanhf(t3) * 3.14159265358979323846f;
    float sn, cs;
    sincosf(rot, &sn, &cs);
    float x_ext = fminf(s*fabsf(cs) + s*fabsf(sn), 1.f);
    float y_ext = fminf(s*fabsf(sn) + s*fabsf(cs), 1.f);
    float txv = trx * (1.f - x_ext);
    float tyv = trY * (1.f - y_ext);
    par[i*6+0] =  s*cs;
    par[i*6+1] = -s*sn;
    par[i*6+2] =  s*sn;
    par[i*6+3] =  s*cs;
    par[i*6+4] =  txv;
    par[i*6+5] =  tyv;
    out_translate[i*2+0] = txv;
    out_translate[i*2+1] = tyv;
}

__global__ void gridsample_kernel(const float* __restrict__ x,
                                  const float* __restrict__ par,
                                  float* __restrict__ out)
{
    int idx = blockIdx.x * blockDim.x + threadIdx.x;
    const int total = ROWS * CIN * PSZ * PSZ;
    if (idx >= total) return;
    int px = idx & 15;
    int py = (idx >> 4) & 15;
    int c  = (idx >> 8) % 3;
    int bp = idx / (3*256);
    int b  = bp >> 6;

    float ta = par[bp*6+0], tb = par[bp*6+1], tc = par[bp*6+2];
    float td = par[bp*6+3], txp = par[bp*6+4], typ = par[bp*6+5];

    float bxv = (2.f*px + 1.f) / 16.f - 1.f;
    float byv = (2.f*py + 1.f) / 16.f - 1.f;
    float gx = ta*bxv + tb*byv + txp;
    float gy = tc*bxv + td*byv + typ;

    float xs = ((gx + 1.f) * (float)WIMG - 1.f) * 0.5f;
    float ys = ((gy + 1.f) * (float)HIMG - 1.f) * 0.5f;
    float x0f = floorf(xs), y0f = floorf(ys);
    float wx = xs - x0f, wy = ys - y0f;
    int x0 = (int)x0f, y0 = (int)y0f;

    const float* img = x + ((size_t)b*3 + c) * (HIMG*WIMG);
    float v00 = 0.f, v01 = 0.f, v10 = 0.f, v11 = 0.f;
    bool xv0 = (x0   >= 0) & (x0   < WIMG);
    bool xv1 = (x0+1 >= 0) & (x0+1 < WIMG);
    bool yv0 = (y0   >= 0) & (y0   < HIMG);
    bool yv1 = (y0+1 >= 0) & (y0+1 < HIMG);
    if (yv0 & xv0) v00 = img[y0*WIMG + x0];
    if (yv0 & xv1) v01 = img[y0*WIMG + x0 + 1];
    if (yv1 & xv0) v10 = img[(y0+1)*WIMG + x0];
    if (yv1 & xv1) v11 = img[(y0+1)*WIMG + x0 + 1];

    out[idx] = v00*(1.f-wx)*(1.f-wy) + v01*wx*(1.f-wy)
             + v10*(1.f-wx)*wy       + v11*wx*wy;
}

// ---------------------------------------------------------------------------
// kernel_launch
// ---------------------------------------------------------------------------
static void cvt(const float* s, __nv_bfloat16* hi, __nv_bfloat16* lo, int n)
{
    cvt_split_kernel<<<(n/4 + 255)/256, 256>>>(s, hi, lo, n/4);
}

extern "C" void kernel_launch(void* const* d_in, const int* in_sizes, int n_in,
                              void* d_out, int out_size)
{
    const float* x        = (const float*)d_in[0];
    const float* conv1_w  = (const float*)d_in[1];
    const float* conv1_b  = (const float*)d_in[2];
    const float* a1_in_w  = (const float*)d_in[3];
    const float* a1_in_b  = (const float*)d_in[4];
    const float* a1_qkv_w = (const float*)d_in[5];
    const float* a1_qkv_b = (const float*)d_in[6];
    const float* a1_out_w = (const float*)d_in[7];
    const float* a1_out_b = (const float*)d_in[8];
    const float* a1_proj_w= (const float*)d_in[9];
    const float* a1_proj_b= (const float*)d_in[10];
    const float* conv2_w  = (const float*)d_in[11];
    const float* conv2_b  = (const float*)d_in[12];
    const float* a2_in_w  = (const float*)d_in[13];
    const float* a2_in_b  = (const float*)d_in[14];
    const float* a2_qkv_w = (const float*)d_in[15];
    const float* a2_qkv_b = (const float*)d_in[16];
    const float* a2_out_w = (const float*)d_in[17];
    const float* a2_out_b = (const float*)d_in[18];
    const float* a2_proj_w= (const float*)d_in[19];
    const float* a2_proj_b= (const float*)d_in[20];
    const float* fc1_w    = (const float*)d_in[21];
    const float* fc1_b    = (const float*)d_in[22];
    const float* fc2_w    = (const float*)d_in[23];
    const float* fc2_b    = (const float*)d_in[24];

    float* out = (float*)d_out;
    float* out_patches   = out;
    float* out_translate = out + ROWS*CIN*PSZ*PSZ;

    float *f1, *y1, *pool, *f2, *y2, *t, *qkv, *att, *o, *h1, *tp, *par, *part;
    __nv_bfloat16 *Ah, *Al, *Bh, *Bl;
    cudaGetSymbolAddress((void**)&f1,   g_f1);
    cudaGetSymbolAddress((void**)&y1,   g_y1);
    cudaGetSymbolAddress((void**)&pool, g_pool);
    cudaGetSymbolAddress((void**)&f2,   g_f2);
    cudaGetSymbolAddress((void**)&y2,   g_y2);
    cudaGetSymbolAddress((void**)&t,    g_t);
    cudaGetSymbolAddress((void**)&qkv,  g_qkv);
    cudaGetSymbolAddress((void**)&att,  g_att);
    cudaGetSymbolAddress((void**)&o,    g_o);
    cudaGetSymbolAddress((void**)&h1,   g_h1);
    cudaGetSymbolAddress((void**)&tp,   g_tp);
    cudaGetSymbolAddress((void**)&par,  g_par);
    cudaGetSymbolAddress((void**)&part, g_part);
    cudaGetSymbolAddress((void**)&Ah,   g_Ah);
    cudaGetSymbolAddress((void**)&Al,   g_Al);
    cudaGetSymbolAddress((void**)&Bh,   g_Bh);
    cudaGetSymbolAddress((void**)&Bl,   g_Bl);

    cudaFuncSetAttribute(attn_kernel,
                         cudaFuncAttributeMaxDynamicSharedMemorySize, ATTN_SMEM);
    cudaFuncSetAttribute(gemm_mma_kernel<1,0>,
                         cudaFuncAttributeMaxDynamicSharedMemorySize, GMM_SMEM);
    cudaFuncSetAttribute(gemm_mma_kernel<3,0>,
                         cudaFuncAttributeMaxDynamicSharedMemorySize, GMM_SMEM);
    cudaFuncSetAttribute(gemm_mma_kernel<1,1>,
                         cudaFuncAttributeMaxDynamicSharedMemorySize, GMM_SMEM);

    const int MN768 = ROWS * EMB;

    // --- conv1 + relu (32,3,128,128) -> (32,64,128,128)
    conv3x3_relu2_kernel<3, 3, 128, 128>
        <<<dim3((128/16)*(128/64), BATCH*8), 256>>>(x, conv1_w, conv1_b, f1);

    // --- attention block 1
    // a1_in: 2048x768, K=16384, split-K=3
    cvt(f1, Ah, Al, ROWS*HW1);
    cvt(a1_in_w, Bh, Bl, EMB*HW1);
    gemm_mma_kernel<3,0><<<dim3(6, 16, 3), 256, GMM_SMEM>>>(
        Ah, Al, Bh, Bl, nullptr, nullptr, ROWS, EMB, HW1, part);
    splitk_reduce_kernel<<<(MN768 + 255)/256, 256>>>(part, a1_in_b, t, MN768, EMB, 3);
    // qkv: 2048x2304, K=768
    cvt(t, Ah, Al, ROWS*EMB);
    cvt(a1_qkv_w, Bh, Bl, 3*EMB*EMB);
    gemm_mma_kernel<1,0><<<dim3(18, 16, 1), 256, GMM_SMEM>>>(
        Ah, Al, Bh, Bl, a1_qkv_b, qkv, ROWS, 3*EMB, EMB, nullptr);
    attn_kernel<<<BATCH*4, 512, ATTN_SMEM>>>(qkv, att);
    // out: 2048x768, K=768, split-K=3
    cvt(att, Ah, Al, ROWS*EMB);
    cvt(a1_out_w, Bh, Bl, EMB*EMB);
    gemm_mma_kernel<3,0><<<dim3(6, 16, 3), 256, GMM_SMEM>>>(
        Ah, Al, Bh, Bl, nullptr, nullptr, ROWS, EMB, EMB, part);
    splitk_reduce_kernel<<<(MN768 + 255)/256, 256>>>(part, a1_out_b, o, MN768, EMB, 3);
    // proj1: 2048x16384, K=768
    cvt(o, Ah, Al, ROWS*EMB);
    cvt(a1_proj_w, Bh, Bl, HW1*EMB);
    gemm_mma_kernel<1,0><<<dim3(128, 16, 1), 256, GMM_SMEM>>>(
        Ah, Al, Bh, Bl, a1_proj_b, y1, ROWS, HW1, EMB, nullptr);

    // --- maxpool
    maxpool_kernel<<<(ROWS*HW2 + 255)/256, 256>>>(y1, pool);

    // --- conv2 + relu (32,64,64,64) -> (32,64,64,64)
    conv3x3_relu2_kernel<64, 8, 64, 64>
        <<<dim3((64/16)*(64/64), BATCH*8), 256>>>(pool, conv2_w, conv2_b, f2);

    // --- attention block 2
    cvt(f2, Ah, Al, ROWS*HW2);
    cvt(a2_in_w, Bh, Bl, EMB*HW2);
    gemm_mma_kernel<3,0><<<dim3(6, 16, 3), 256, GMM_SMEM>>>(
        Ah, Al, Bh, Bl, nullptr, nullptr, ROWS, EMB, HW2, part);
    splitk_reduce_kernel<<<(MN768 + 255)/256, 256>>>(part, a2_in_b, t, MN768, EMB, 3);
    cvt(t, Ah, Al, ROWS*EMB);
    cvt(a2_qkv_w, Bh, Bl, 3*EMB*EMB);
    gemm_mma_kernel<1,0><<<dim3(18, 16, 1), 256, GMM_SMEM>>>(
        Ah, Al, Bh, Bl, a2_qkv_b, qkv, ROWS, 3*EMB, EMB, nullptr);
    attn_kernel<<<BATCH*4, 512, ATTN_SMEM>>>(qkv, att);
    cvt(att, Ah, Al, ROWS*EMB);
    cvt(a2_out_w, Bh, Bl, EMB*EMB);
    gemm_mma_kernel<3,0><<<dim3(6, 16, 3), 256, GMM_SMEM>>>(
        Ah, Al, Bh, Bl, nullptr, nullptr, ROWS, EMB, EMB, part);
    splitk_reduce_kernel<<<(MN768 + 255)/256, 256>>>(part, a2_out_b, o, MN768, EMB, 3);
    // proj2: 2048x4096, K=768
    cvt(o, Ah, Al, ROWS*EMB);
    cvt(a2_proj_w, Bh, Bl, HW2*EMB);
    gemm_mma_kernel<1,0><<<dim3(32, 16, 1), 256, GMM_SMEM>>>(
        Ah, Al, Bh, Bl, a2_proj_b, y2, ROWS, HW2, EMB, nullptr);

    // --- head
    // fc1: 2048x2048, K=4096, fused relu
    cvt(y2, Ah, Al, ROWS*HW2);
    cvt(fc1_w, Bh, Bl, HC2*HW2);
    gemm_mma_kernel<1,1><<<dim3(16, 16, 1), 256, GMM_SMEM>>>(
        Ah, Al, Bh, Bl, fc1_b, h1, ROWS, HC2, HW2, nullptr);
    fc2_kernel<<<(ROWS*32 + 255)/256, 256>>>(h1, fc2_w, fc2_b, tp);
    params_kernel<<<(ROWS + 255)/256, 256>>>(tp, par, out_translate);
    gridsample_kernel<<<(ROWS*CIN*PSZ*PSZ + 255)/256, 256>>>(x, par, out_patches);
}

// round 13
// speedup vs baseline: 2.2666x; 1.0018x over previous
#include <cuda_runtime.h>
#include <cuda_bf16.h>
#include <cstdint>
#include <math.h>

// ---------------------------------------------------------------------------
// Problem constants
// ---------------------------------------------------------------------------
#define BATCH 32
#define CIN   3
#define HIMG  128
#define WIMG  128
#define PSZ   16
#define EMB   768
#define DH    192
#define ROWS  2048         // BATCH * 64
#define HW1   16384
#define HW2   4096
#define HC2   2048

typedef unsigned long long u64;

// ---------------------------------------------------------------------------
// helpers
// ---------------------------------------------------------------------------
__device__ __forceinline__ uint32_t smem_to_u32(const void* p) {
    uint32_t a;
    asm("{ .reg .u64 t; cvta.to.shared.u64 t, %1; cvt.u32.u64 %0, t; }"
        : "=r"(a) : "l"(p));
    return a;
}

#define CP_ASYNC16(saddr, gptr) \
    asm volatile("cp.async.cg.shared.global [%0], [%1], 16;" \
        :: "r"(saddr), "l"(gptr) : "memory")
#define CP_COMMIT() asm volatile("cp.async.commit_group;" ::: "memory")
#define CP_WAIT1()  asm volatile("cp.async.wait_group 1;" ::: "memory")
#define CP_WAIT0()  asm volatile("cp.async.wait_group 0;" ::: "memory")

__device__ __forceinline__ void ldsm4(uint32_t* r, uint32_t saddr) {
    asm volatile("ldmatrix.sync.aligned.m8n8.x4.shared.b16 {%0,%1,%2,%3}, [%4];"
        : "=r"(r[0]), "=r"(r[1]), "=r"(r[2]), "=r"(r[3]) : "r"(saddr));
}
__device__ __forceinline__ void mma_bf16(float* d, const uint32_t* a, const uint32_t* b) {
    asm volatile("mma.sync.aligned.m16n8k16.row.col.f32.bf16.bf16.f32 "
        "{%0,%1,%2,%3},{%4,%5,%6,%7},{%8,%9},{%0,%1,%2,%3};"
        : "+f"(d[0]), "+f"(d[1]), "+f"(d[2]), "+f"(d[3])
        : "r"(a[0]), "r"(a[1]), "r"(a[2]), "r"(a[3]), "r"(b[0]), "r"(b[1]));
}

// f32x2 helpers (FFMA2 for the convs)
__device__ __forceinline__ u64 pk2(float lo, float hi) {
    u64 r; asm("mov.b64 %0, {%1,%2};" : "=l"(r) : "f"(lo), "f"(hi)); return r;
}
__device__ __forceinline__ void fma2(u64& d, u64 a, u64 b) {
    asm("fma.rn.f32x2 %0, %1, %2, %0;" : "+l"(d) : "l"(a), "l"(b));
}
__device__ __forceinline__ float2 upk2(u64 v) {
    float2 f; asm("mov.b64 {%0,%1}, %2;" : "=f"(f.x), "=f"(f.y) : "l"(v)); return f;
}

// ---------------------------------------------------------------------------
// Scratch (device globals; no runtime allocation allowed)
// ---------------------------------------------------------------------------
__device__ float g_f1  [ROWS * HW1];
__device__ float g_y1  [ROWS * HW1];
__device__ float g_pool[ROWS * HW2];
__device__ float g_f2  [ROWS * HW2];
__device__ float g_y2  [ROWS * HW2];
__device__ float g_t   [ROWS * EMB];
__device__ float g_qkv [ROWS * 3 * EMB];
__device__ float g_att [ROWS * EMB];
__device__ float g_o   [ROWS * EMB];
__device__ float g_h1  [ROWS * HC2];
__device__ float g_tp  [ROWS * 4];
__device__ float g_par [ROWS * 6];
__device__ float g_part[3 * ROWS * EMB];            // split-K partials
__device__ __nv_bfloat16 g_Ah[ROWS * HW1];          // A hi
__device__ __nv_bfloat16 g_Al[ROWS * HW1];          // A lo
__device__ __nv_bfloat16 g_Bh[HW1 * EMB];           // B hi
__device__ __nv_bfloat16 g_Bl[HW1 * EMB];           // B lo

// ---------------------------------------------------------------------------
// fp32 -> (bf16 hi, bf16 lo) split conversion, vectorized x4
// ---------------------------------------------------------------------------
__global__ void cvt_split_kernel(const float* __restrict__ s,
                                 __nv_bfloat16* __restrict__ hi,
                                 __nv_bfloat16* __restrict__ lo, int n4)
{
    int i = blockIdx.x * blockDim.x + threadIdx.x;
    if (i >= n4) return;
    float4 v = ((const float4*)s)[i];
    __nv_bfloat16 h0 = __float2bfloat16(v.x);
    __nv_bfloat16 h1 = __float2bfloat16(v.y);
    __nv_bfloat16 h2 = __float2bfloat16(v.z);
    __nv_bfloat16 h3 = __float2bfloat16(v.w);
    __nv_bfloat16 l0 = __float2bfloat16(v.x - __bfloat162float(h0));
    __nv_bfloat16 l1 = __float2bfloat16(v.y - __bfloat162float(h1));
    __nv_bfloat16 l2 = __float2bfloat16(v.z - __bfloat162float(h2));
    __nv_bfloat16 l3 = __float2bfloat16(v.w - __bfloat162float(h3));
    ((__nv_bfloat162*)hi)[2*i  ] = __nv_bfloat162(h0, h1);
    ((__nv_bfloat162*)hi)[2*i+1] = __nv_bfloat162(h2, h3);
    ((__nv_bfloat162*)lo)[2*i  ] = __nv_bfloat162(l0, l1);
    ((__nv_bfloat162*)lo)[2*i+1] = __nv_bfloat162(l2, l3);
}

// ---------------------------------------------------------------------------
// Tensor-core GEMM via mma.sync m16n8k16 bf16, 3-split (Ah*Bh + Ah*Bl + Al*Bh).
// C[M,N] = A[M,K] @ B[N,K]^T (+bias,+relu). BM=128, BN=128, BK=32.
// 256 thr = 8 warps (2m x 4n), warp tile 64x32. cp.async double buffering.
// smem rows padded to 40 bf16 (80B) -> conflict-free ldmatrix.
// ---------------------------------------------------------------------------
#define TROW   40                    // bf16 per smem row (32 data + 8 pad)
#define TBYTES (128 * TROW * 2)      // one 128x32 tile = 10240 B
// tile buffer byte offset: matrix m (0=Ah,1=Al,2=Bh,3=Bl), buffer b
#define TOFF(m, b) ((uint32_t)(((m) * 2 + (b)) * TBYTES))
#define GMM_SMEM (8 * TBYTES)        // 81920 B

template<int KSPLIT, int RELU>
__global__ void __launch_bounds__(256, 2)
gemm_mma_kernel(const __nv_bfloat16* __restrict__ Ah, const __nv_bfloat16* __restrict__ Al,
                const __nv_bfloat16* __restrict__ Bh, const __nv_bfloat16* __restrict__ Bl,
                const float* __restrict__ bias, float* __restrict__ C,
                int M, int N, int K, float* __restrict__ part)
{
    extern __shared__ __align__(16) char smbuf[];
    const uint32_t sb = smem_to_u32(smbuf);
    const int tid  = threadIdx.x;
    const int lane = tid & 31;
    const int wid  = tid >> 5;
    const int wm   = (wid >> 2) * 64;   // 0 / 64
    const int wn   = (wid & 3) * 32;    // 0 / 32 / 64 / 96
    const int bm   = blockIdx.y * 128;
    const int bn   = blockIdx.x * 128;

    // k-tile range (BK=32 per tile), uneven split allowed
    const int tiles = K >> 5;
    int t0 = 0, t1 = tiles;
    if (KSPLIT > 1) {
        int per = tiles / KSPLIT, rem = tiles - per * KSPLIT;
        int z = blockIdx.z;
        t0 = z * per + (z < rem ? z : rem);
        t1 = t0 + per + (z < rem ? 1 : 0);
    }

    // loader lane mapping: v = tid + half*256 -> row = v>>2, cv = v&3
    const int lrow0 = tid >> 2, lcv0 = tid & 3;
    const int lrow1 = (tid + 256) >> 2, lcv1 = (tid + 256) & 3;

    // ldmatrix lane offsets
    const int a_row = lane & 15;
    const int a_colb = ((lane >> 4) * 8) * 2;              // byte offset in row
    const int b_row = ((lane >> 4) & 1) * 8 + (lane & 7);
    const int b_colb = (((lane >> 3) & 1) * 8) * 2;

    float d[4][4][4];
    #pragma unroll
    for (int i = 0; i < 4; i++)
        #pragma unroll
        for (int j = 0; j < 4; j++)
            #pragma unroll
            for (int q = 0; q < 4; q++) d[i][j][q] = 0.f;

    // ---- issue loads for tile t0 into buffer 0
    {
        const int kb = t0 << 5;
        uint32_t s0 = (uint32_t)(lrow0 * 80 + lcv0 * 16);
        uint32_t s1 = (uint32_t)(lrow1 * 80 + lcv1 * 16);
        size_t ga0 = (size_t)(bm + lrow0) * K + kb + lcv0 * 8;
        size_t ga1 = (size_t)(bm + lrow1) * K + kb + lcv1 * 8;
        size_t gb0 = (size_t)(bn + lrow0) * K + kb + lcv0 * 8;
        size_t gb1 = (size_t)(bn + lrow1) * K + kb + lcv1 * 8;
        CP_ASYNC16(sb + TOFF(0,0) + s0, Ah + ga0);
        CP_ASYNC16(sb + TOFF(0,0) + s1, Ah + ga1);
        CP_ASYNC16(sb + TOFF(1,0) + s0, Al + ga0);
        CP_ASYNC16(sb + TOFF(1,0) + s1, Al + ga1);
        CP_ASYNC16(sb + TOFF(2,0) + s0, Bh + gb0);
        CP_ASYNC16(sb + TOFF(2,0) + s1, Bh + gb1);
        CP_ASYNC16(sb + TOFF(3,0) + s0, Bl + gb0);
        CP_ASYNC16(sb + TOFF(3,0) + s1, Bl + gb1);
        CP_COMMIT();
    }

    int buf = 0;
    for (int t = t0; t < t1; t++) {
        const bool hasNext = (t + 1 < t1);
        if (hasNext) {
            const int kb = (t + 1) << 5;
            const int nb = buf ^ 1;
            uint32_t s0 = (uint32_t)(lrow0 * 80 + lcv0 * 16);
            uint32_t s1 = (uint32_t)(lrow1 * 80 + lcv1 * 16);
            size_t ga0 = (size_t)(bm + lrow0) * K + kb + lcv0 * 8;
            size_t ga1 = (size_t)(bm + lrow1) * K + kb + lcv1 * 8;
            size_t gb0 = (size_t)(bn + lrow0) * K + kb + lcv0 * 8;
            size_t gb1 = (size_t)(bn + lrow1) * K + kb + lcv1 * 8;
            CP_ASYNC16(sb + TOFF(0,nb) + s0, Ah + ga0);
            CP_ASYNC16(sb + TOFF(0,nb) + s1, Ah + ga1);
            CP_ASYNC16(sb + TOFF(1,nb) + s0, Al + ga0);
            CP_ASYNC16(sb + TOFF(1,nb) + s1, Al + ga1);
            CP_ASYNC16(sb + TOFF(2,nb) + s0, Bh + gb0);
            CP_ASYNC16(sb + TOFF(2,nb) + s1, Bh + gb1);
            CP_ASYNC16(sb + TOFF(3,nb) + s0, Bl + gb0);
            CP_ASYNC16(sb + TOFF(3,nb) + s1, Bl + gb1);
            CP_COMMIT();
            CP_WAIT1();
        } else {
            CP_WAIT0();
        }
        __syncthreads();

        #pragma unroll
        for (int s = 0; s < 2; s++) {
            const uint32_t scolb = (uint32_t)(s * 32);   // s*16 bf16 = 32 B
            uint32_t ah[4][4], bh[2][4], bl[2][4];
            #pragma unroll
            for (int mt = 0; mt < 4; mt++)
                ldsm4(ah[mt], sb + TOFF(0,buf)
                      + (uint32_t)((wm + mt*16 + a_row) * 80) + scolb + a_colb);
            #pragma unroll
            for (int np = 0; np < 2; np++)
                ldsm4(bh[np], sb + TOFF(2,buf)
                      + (uint32_t)((wn + np*16 + b_row) * 80) + scolb + b_colb);
            #pragma unroll
            for (int np = 0; np < 2; np++)
                ldsm4(bl[np], sb + TOFF(3,buf)
                      + (uint32_t)((wn + np*16 + b_row) * 80) + scolb + b_colb);
            // Ah * Bh
            #pragma unroll
            for (int mt = 0; mt < 4; mt++)
                #pragma unroll
                for (int nt = 0; nt < 4; nt++)
                    mma_bf16(d[mt][nt], ah[mt], &bh[nt>>1][(nt&1)*2]);
            // Ah * Bl
            #pragma unroll
            for (int mt = 0; mt < 4; mt++)
                #pragma unroll
                for (int nt = 0; nt < 4; nt++)
                    mma_bf16(d[mt][nt], ah[mt], &bl[nt>>1][(nt&1)*2]);
            // Al * Bh (reuse ah regs)
            #pragma unroll
            for (int mt = 0; mt < 4; mt++)
                ldsm4(ah[mt], sb + TOFF(1,buf)
                      + (uint32_t)((wm + mt*16 + a_row) * 80) + scolb + a_colb);
            #pragma unroll
            for (int mt = 0; mt < 4; mt++)
                #pragma unroll
                for (int nt = 0; nt < 4; nt++)
                    mma_bf16(d[mt][nt], ah[mt], &bh[nt>>1][(nt&1)*2]);
        }
        __syncthreads();
        buf ^= 1;
    }

    // ---- epilogue
    const int er = lane >> 2;          // 0..7
    const int ec = (lane & 3) * 2;     // 0,2,4,6
    if (KSPLIT > 1) {
        float* P = part + (size_t)blockIdx.z * M * N;
        #pragma unroll
        for (int mt = 0; mt < 4; mt++) {
            #pragma unroll
            for (int nt = 0; nt < 4; nt++) {
                int r = bm + wm + mt*16 + er;
                int c = bn + wn + nt*8 + ec;
                *(float2*)(P + (size_t)r * N + c)       = make_float2(d[mt][nt][0], d[mt][nt][1]);
                *(float2*)(P + (size_t)(r + 8) * N + c) = make_float2(d[mt][nt][2], d[mt][nt][3]);
            }
        }
    } else {
        #pragma unroll
        for (int mt = 0; mt < 4; mt++) {
            #pragma unroll
            for (int nt = 0; nt < 4; nt++) {
                int r = bm + wm + mt*16 + er;
                int c = bn + wn + nt*8 + ec;
                float b0 = bias[c], b1 = bias[c+1];
                float v0 = d[mt][nt][0] + b0, v1 = d[mt][nt][1] + b1;
                float v2 = d[mt][nt][2] + b0, v3 = d[mt][nt][3] + b1;
                if (RELU) {
                    v0 = fmaxf(v0, 0.f); v1 = fmaxf(v1, 0.f);
                    v2 = fmaxf(v2, 0.f); v3 = fmaxf(v3, 0.f);
                }
                *(float2*)(C + (size_t)r * N + c)       = make_float2(v0, v1);
                *(float2*)(C + (size_t)(r + 8) * N + c) = make_float2(v2, v3);
            }
        }
    }
}

// split-K reduce: C = sum_z part[z] + bias   (S <= 3)
__global__ void splitk_reduce_kernel(const float* __restrict__ part,
                                     const float* __restrict__ bias,
                                     float* __restrict__ C, int MN, int N, int S)
{
    int idx = blockIdx.x * blockDim.x + threadIdx.x;
    if (idx >= MN) return;
    float s = bias[idx % N] + part[idx];
    if (S > 1) s += part[idx + MN];
    if (S > 2) s += part[idx + 2*MN];
    C[idx] = s;
}

// ---------------------------------------------------------------------------
// 3x3 SAME conv + relu with FFMA2 (unchanged from round 7)
// ---------------------------------------------------------------------------
template<int IC, int ICC, int HH, int WW>
__global__ void __launch_bounds__(256)
conv3x3_relu2_kernel(const float* __restrict__ in, const float* __restrict__ w,
                     const float* __restrict__ bias, float* __restrict__ out)
{
    __shared__ float  sIn[ICC][66][18];
    __shared__ float2 sW2[8][ICC][9];

    const int tx = threadIdx.x & 15;
    const int ty = threadIdx.x >> 4;
    const int tilesX = WW / 16;
    const int bx = (blockIdx.x % tilesX) * 16;
    const int by = (blockIdx.x / tilesX) * 64;
    const int b   = blockIdx.y >> 3;
    const int ocg = (blockIdx.y & 7) * 8;

    u64 a01[8], a23[8];
    #pragma unroll
    for (int oc = 0; oc < 8; oc++) { a01[oc] = 0ull; a23[oc] = 0ull; }

    for (int icc = 0; icc < IC; icc += ICC) {
        for (int i = threadIdx.x; i < ICC*66*18; i += 256) {
            int col = i % 18; int t = i / 18; int row = t % 66; int ic = t / 66;
            int gx = bx + col - 1, gy = by + row - 1;
            float v = 0.f;
            if (gx >= 0 && gx < WW && gy >= 0 && gy < HH)
                v = in[(((size_t)b*IC + icc + ic)*HH + gy)*WW + gx];
            sIn[ic][row][col] = v;
        }
        for (int i = threadIdx.x; i < 8*ICC*9; i += 256) {
            int kk = i % 9; int t = i / 9; int ic = t % ICC; int oc = t / ICC;
            float wv = w[((ocg + oc)*IC + icc + ic)*9 + kk];
            sW2[oc][ic][kk] = make_float2(wv, wv);
        }
        __syncthreads();

        #pragma unroll
        for (int ic = 0; ic < ICC; ic++) {
            #pragma unroll
            for (int ky = 0; ky < 3; ky++) {
                #pragma unroll
                for (int kx = 0; kx < 3; kx++) {
                    float iv0 = sIn[ic][ty      + ky][tx + kx];
                    float iv1 = sIn[ic][ty + 16 + ky][tx + kx];
                    float iv2 = sIn[ic][ty + 32 + ky][tx + kx];
                    float iv3 = sIn[ic][ty + 48 + ky][tx + kx];
                    u64 p01 = pk2(iv0, iv1);
                    u64 p23 = pk2(iv2, iv3);
                    #pragma unroll
                    for (int oc = 0; oc < 8; oc++) {
                        u64 wv = *(const u64*)&sW2[oc][ic][ky*3 + kx];
                        fma2(a01[oc], p01, wv);
                        fma2(a23[oc], p23, wv);
                    }
                }
            }
        }
        __syncthreads();
    }

    #pragma unroll
    for (int oc = 0; oc < 8; oc++) {
        float bv = bias[ocg + oc];
        float2 v01 = upk2(a01[oc]);
        float2 v23 = upk2(a23[oc]);
        size_t base = (((size_t)b*64 + ocg + oc)*HH + by + ty)*WW + bx + tx;
        out[base            ] = fmaxf(v01.x + bv, 0.f);
        out[base + 16ull*WW ] = fmaxf(v01.y + bv, 0.f);
        out[base + 32ull*WW ] = fmaxf(v23.x + bv, 0.f);
        out[base + 48ull*WW ] = fmaxf(v23.y + bv, 0.f);
    }
}

// ---------------------------------------------------------------------------
// MHA core (unchanged)
// ---------------------------------------------------------------------------
#define QKV_STRIDE 193
#define SC_STRIDE  65
#define ATTN_SMEM  ((3*64*QKV_STRIDE + 64*SC_STRIDE) * (int)sizeof(float))

__global__ void attn_kernel(const float* __restrict__ qkv, float* __restrict__ out)
{
    extern __shared__ float sm[];
    float* sQ = sm;
    float* sK = sQ + 64*QKV_STRIDE;
    float* sV = sK + 64*QKV_STRIDE;
    float* sS = sV + 64*QKV_STRIDE;

    const int bh = blockIdx.x;
    const int b  = bh >> 2;
    const int h  = bh & 3;
    const int base = b * 64;
    const float scale = 0.07216878364870323f; // 1/sqrt(192)

    for (int i = threadIdx.x; i < 64*DH; i += 512) {
        int r = i / DH, c = i % DH;
        size_t off = (size_t)(base + r)*2304 + h*DH + c;
        sQ[r*QKV_STRIDE + c] = qkv[off];
        sK[r*QKV_STRIDE + c] = qkv[off + 768];
        sV[r*QKV_STRIDE + c] = qkv[off + 1536];
    }
    __syncthreads();

    for (int e = threadIdx.x; e < 64*64; e += 512) {
        int i = e >> 6, j = e & 63;
        const float* q = sQ + i*QKV_STRIDE;
        const float* k = sK + j*QKV_STRIDE;
        float s = 0.f;
        #pragma unroll 8
        for (int d = 0; d < DH; d++) s = fmaf(q[d], k[d], s);
        sS[i*SC_STRIDE + j] = s * scale;
    }
    __syncthreads();

    if (threadIdx.x < 64) {
        float* row = sS + threadIdx.x * SC_STRIDE;
        float mx = row[0];
        #pragma unroll 8
        for (int j = 1; j < 64; j++) mx = fmaxf(mx, row[j]);
        float sum = 0.f;
        #pragma unroll 8
        for (int j = 0; j < 64; j++) { float e = __expf(row[j] - mx); row[j] = e; sum += e; }
        float inv = 1.f / sum;
        #pragma unroll 8
        for (int j = 0; j < 64; j++) row[j] *= inv;
    }
    __syncthreads();

    for (int e = threadIdx.x; e < 64*DH; e += 512) {
        int i = e / DH, d = e % DH;
        const float* p = sS + i*SC_STRIDE;
        float s = 0.f;
        #pragma unroll 8
        for (int j = 0; j < 64; j++) s = fmaf(p[j], sV[j*QKV_STRIDE + d], s);
        out[(size_t)(base + i)*EMB + h*DH + d] = s;
    }
}

// ---------------------------------------------------------------------------
// 2x2 maxpool, fc2, params, gridsample (unchanged)
// ---------------------------------------------------------------------------
__global__ void maxpool_kernel(const float* __restrict__ in, float* __restrict__ out)
{
    int idx = blockIdx.x * blockDim.x + threadIdx.x;
    if (idx >= ROWS * HW2) return;
    int ox = idx & 63;
    int oy = (idx >> 6) & 63;
    int cb = idx >> 12;
    const float* p = in + ((size_t)cb*128 + oy*2)*128 + ox*2;
    out[idx] = fmaxf(fmaxf(p[0], p[1]), fmaxf(p[128], p[129]));
}

__global__ void fc2_kernel(const float* __restrict__ h1, const float* __restrict__ w,
                           const float* __restrict__ bias, float* __restrict__ tp)
{
    int warp = (blockIdx.x * blockDim.x + threadIdx.x) >> 5;
    int lane = threadIdx.x & 31;
    if (warp >= ROWS) return;
    const float* row = h1 + (size_t)warp * HC2;
    float a0 = 0.f, a1 = 0.f, a2 = 0.f, a3 = 0.f;
    for (int k = lane; k < HC2; k += 32) {
        float hv = row[k];
        a0 = fmaf(hv, w[k],          a0);
        a1 = fmaf(hv, w[HC2   + k],  a1);
        a2 = fmaf(hv, w[2*HC2 + k],  a2);
        a3 = fmaf(hv, w[3*HC2 + k],  a3);
    }
    #pragma unroll
    for (int o = 16; o > 0; o >>= 1) {
        a0 += __shfl_xor_sync(0xffffffffu, a0, o);
        a1 += __shfl_xor_sync(0xffffffffu, a1, o);
        a2 += __shfl_xor_sync(0xffffffffu, a2, o);
        a3 += __shfl_xor_sync(0xffffffffu, a3, o);
    }
    if (lane == 0) {
        tp[warp*4 + 0] = a0 + bias[0];
        tp[warp*4 + 1] = a1 + bias[1];
        tp[warp*4 + 2] = a2 + bias[2];
        tp[warp*4 + 3] = a3 + bias[3];
    }
}

__global__ void params_kernel(const float* __restrict__ tp, float* __restrict__ par,
                              float* __restrict__ out_translate)
{
    int i = blockIdx.x * blockDim.x + threadIdx.x;
    if (i >= ROWS) return;
    float t0 = tp[i*4+0], t1 = tp[i*4+1], t2 = tp[i*4+2], t3 = tp[i*4+3];
    float trx = tanhf(t0);
    float trY = tanhf(t1);
    float s   = 0.3f / (1.f + expf(-t2));
    float rot = tanhf(t3) * 3.14159265358979323846f;
    float sn, cs;
    sincosf(rot, &sn, &cs);
    float x_ext = fminf(s*fabsf(cs) + s*fabsf(sn), 1.f);
    float y_ext = fminf(s*fabsf(sn) + s*fabsf(cs), 1.f);
    float txv = trx * (1.f - x_ext);
    float tyv = trY * (1.f - y_ext);
    par[i*6+0] =  s*cs;
    par[i*6+1] = -s*sn;
    par[i*6+2] =  s*sn;
    par[i*6+3] =  s*cs;
    par[i*6+4] =  txv;
    par[i*6+5] =  tyv;
    out_translate[i*2+0] = txv;
    out_translate[i*2+1] = tyv;
}

__global__ void gridsample_kernel(const float* __restrict__ x,
                                  const float* __restrict__ par,
                                  float* __restrict__ out)
{
    int idx = blockIdx.x * blockDim.x + threadIdx.x;
    const int total = ROWS * CIN * PSZ * PSZ;
    if (idx >= total) return;
    int px = idx & 15;
    int py = (idx >> 4) & 15;
    int c  = (idx >> 8) % 3;
    int bp = idx / (3*256);
    int b  = bp >> 6;

    float ta = par[bp*6+0], tb = par[bp*6+1], tc = par[bp*6+2];
    float td = par[bp*6+3], txp = par[bp*6+4], typ = par[bp*6+5];

    float bxv = (2.f*px + 1.f) / 16.f - 1.f;
    float byv = (2.f*py + 1.f) / 16.f - 1.f;
    float gx = ta*bxv + tb*byv + txp;
    float gy = tc*bxv + td*byv + typ;

    float xs = ((gx + 1.f) * (float)WIMG - 1.f) * 0.5f;
    float ys = ((gy + 1.f) * (float)HIMG - 1.f) * 0.5f;
    float x0f = floorf(xs), y0f = floorf(ys);
    float wx = xs - x0f, wy = ys - y0f;
    int x0 = (int)x0f, y0 = (int)y0f;

    const float* img = x + ((size_t)b*3 + c) * (HIMG*WIMG);
    float v00 = 0.f, v01 = 0.f, v10 = 0.f, v11 = 0.f;
    bool xv0 = (x0   >= 0) & (x0   < WIMG);
    bool xv1 = (x0+1 >= 0) & (x0+1 < WIMG);
    bool yv0 = (y0   >= 0) & (y0   < HIMG);
    bool yv1 = (y0+1 >= 0) & (y0+1 < HIMG);
    if (yv0 & xv0) v00 = img[y0*WIMG + x0];
    if (yv0 & xv1) v01 = img[y0*WIMG + x0 + 1];
    if (yv1 & xv0) v10 = img[(y0+1)*WIMG + x0];
    if (yv1 & xv1) v11 = img[(y0+1)*WIMG + x0 + 1];

    out[idx] = v00*(1.f-wx)*(1.f-wy) + v01*wx*(1.f-wy)
             + v10*(1.f-wx)*wy       + v11*wx*wy;
}

// ---------------------------------------------------------------------------
// kernel_launch
// ---------------------------------------------------------------------------
static void cvt(const float* s, __nv_bfloat16* hi, __nv_bfloat16* lo, int n)
{
    cvt_split_kernel<<<(n/4 + 255)/256, 256>>>(s, hi, lo, n/4);
}

extern "C" void kernel_launch(void* const* d_in, const int* in_sizes, int n_in,
                              void* d_out, int out_size)
{
    const float* x        = (const float*)d_in[0];
    const float* conv1_w  = (const float*)d_in[1];
    const float* conv1_b  = (const float*)d_in[2];
    const float* a1_in_w  = (const float*)d_in[3];
    const float* a1_in_b  = (const float*)d_in[4];
    const float* a1_qkv_w = (const float*)d_in[5];
    const float* a1_qkv_b = (const float*)d_in[6];
    const float* a1_out_w = (const float*)d_in[7];
    const float* a1_out_b = (const float*)d_in[8];
    const float* a1_proj_w= (const float*)d_in[9];
    const float* a1_proj_b= (const float*)d_in[10];
    const float* conv2_w  = (const float*)d_in[11];
    const float* conv2_b  = (const float*)d_in[12];
    const float* a2_in_w  = (const float*)d_in[13];
    const float* a2_in_b  = (const float*)d_in[14];
    const float* a2_qkv_w = (const float*)d_in[15];
    const float* a2_qkv_b = (const float*)d_in[16];
    const float* a2_out_w = (const float*)d_in[17];
    const float* a2_out_b = (const float*)d_in[18];
    const float* a2_proj_w= (const float*)d_in[19];
    const float* a2_proj_b= (const float*)d_in[20];
    const float* fc1_w    = (const float*)d_in[21];
    const float* fc1_b    = (const float*)d_in[22];
    const float* fc2_w    = (const float*)d_in[23];
    const float* fc2_b    = (const float*)d_in[24];

    float* out = (float*)d_out;
    float* out_patches   = out;
    float* out_translate = out + ROWS*CIN*PSZ*PSZ;

    float *f1, *y1, *pool, *f2, *y2, *t, *qkv, *att, *o, *h1, *tp, *par, *part;
    __nv_bfloat16 *Ah, *Al, *Bh, *Bl;
    cudaGetSymbolAddress((void**)&f1,   g_f1);
    cudaGetSymbolAddress((void**)&y1,   g_y1);
    cudaGetSymbolAddress((void**)&pool, g_pool);
    cudaGetSymbolAddress((void**)&f2,   g_f2);
    cudaGetSymbolAddress((void**)&y2,   g_y2);
    cudaGetSymbolAddress((void**)&t,    g_t);
    cudaGetSymbolAddress((void**)&qkv,  g_qkv);
    cudaGetSymbolAddress((void**)&att,  g_att);
    cudaGetSymbolAddress((void**)&o,    g_o);
    cudaGetSymbolAddress((void**)&h1,   g_h1);
    cudaGetSymbolAddress((void**)&tp,   g_tp);
    cudaGetSymbolAddress((void**)&par,  g_par);
    cudaGetSymbolAddress((void**)&part, g_part);
    cudaGetSymbolAddress((void**)&Ah,   g_Ah);
    cudaGetSymbolAddress((void**)&Al,   g_Al);
    cudaGetSymbolAddress((void**)&Bh,   g_Bh);
    cudaGetSymbolAddress((void**)&Bl,   g_Bl);

    cudaFuncSetAttribute(attn_kernel,
                         cudaFuncAttributeMaxDynamicSharedMemorySize, ATTN_SMEM);
    cudaFuncSetAttribute(gemm_mma_kernel<1,0>,
                         cudaFuncAttributeMaxDynamicSharedMemorySize, GMM_SMEM);
    cudaFuncSetAttribute(gemm_mma_kernel<3,0>,
                         cudaFuncAttributeMaxDynamicSharedMemorySize, GMM_SMEM);
    cudaFuncSetAttribute(gemm_mma_kernel<1,1>,
                         cudaFuncAttributeMaxDynamicSharedMemorySize, GMM_SMEM);

    const int MN768 = ROWS * EMB;

    // --- conv1 + relu (32,3,128,128) -> (32,64,128,128)
    conv3x3_relu2_kernel<3, 3, 128, 128>
        <<<dim3((128/16)*(128/64), BATCH*8), 256>>>(x, conv1_w, conv1_b, f1);

    // --- attention block 1
    // a1_in: 2048x768, K=16384, split-K=3
    cvt(f1, Ah, Al, ROWS*HW1);
    cvt(a1_in_w, Bh, Bl, EMB*HW1);
    gemm_mma_kernel<3,0><<<dim3(6, 16, 3), 256, GMM_SMEM>>>(
        Ah, Al, Bh, Bl, nullptr, nullptr, ROWS, EMB, HW1, part);
    splitk_reduce_kernel<<<(MN768 + 255)/256, 256>>>(part, a1_in_b, t, MN768, EMB, 3);
    // qkv: 2048x2304, K=768
    cvt(t, Ah, Al, ROWS*EMB);
    cvt(a1_qkv_w, Bh, Bl, 3*EMB*EMB);
    gemm_mma_kernel<1,0><<<dim3(18, 16, 1), 256, GMM_SMEM>>>(
        Ah, Al, Bh, Bl, a1_qkv_b, qkv, ROWS, 3*EMB, EMB, nullptr);
    attn_kernel<<<BATCH*4, 512, ATTN_SMEM>>>(qkv, att);
    // out: 2048x768, K=768, split-K=3
    cvt(att, Ah, Al, ROWS*EMB);
    cvt(a1_out_w, Bh, Bl, EMB*EMB);
    gemm_mma_kernel<3,0><<<dim3(6, 16, 3), 256, GMM_SMEM>>>(
        Ah, Al, Bh, Bl, nullptr, nullptr, ROWS, EMB, EMB, part);
    splitk_reduce_kernel<<<(MN768 + 255)/256, 256>>>(part, a1_out_b, o, MN768, EMB, 3);
    // proj1: 2048x16384, K=768
    cvt(o, Ah, Al, ROWS*EMB);
    cvt(a1_proj_w, Bh, Bl, HW1*EMB);
    gemm_mma_kernel<1,0><<<dim3(128, 16, 1), 256, GMM_SMEM>>>(
        Ah, Al, Bh, Bl, a1_proj_b, y1, ROWS, HW1, EMB, nullptr);

    // --- maxpool
    maxpool_kernel<<<(ROWS*HW2 + 255)/256, 256>>>(y1, pool);

    // --- conv2 + relu (32,64,64,64) -> (32,64,64,64)
    conv3x3_relu2_kernel<64, 8, 64, 64>
        <<<dim3((64/16)*(64/64), BATCH*8), 256>>>(pool, conv2_w, conv2_b, f2);

    // --- attention block 2
    cvt(f2, Ah, Al, ROWS*HW2);
    cvt(a2_in_w, Bh, Bl, EMB*HW2);
    gemm_mma_kernel<3,0><<<dim3(6, 16, 3), 256, GMM_SMEM>>>(
        Ah, Al, Bh, Bl, nullptr, nullptr, ROWS, EMB, HW2, part);
    splitk_reduce_kernel<<<(MN768 + 255)/256, 256>>>(part, a2_in_b, t, MN768, EMB, 3);
    cvt(t, Ah, Al, ROWS*EMB);
    cvt(a2_qkv_w, Bh, Bl, 3*EMB*EMB);
    gemm_mma_kernel<1,0><<<dim3(18, 16, 1), 256, GMM_SMEM>>>(
        Ah, Al, Bh, Bl, a2_qkv_b, qkv, ROWS, 3*EMB, EMB, nullptr);
    attn_kernel<<<BATCH*4, 512, ATTN_SMEM>>>(qkv, att);
    cvt(att, Ah, Al, ROWS*EMB);
    cvt(a2_out_w, Bh, Bl, EMB*EMB);
    gemm_mma_kernel<3,0><<<dim3(6, 16, 3), 256, GMM_SMEM>>>(
        Ah, Al, Bh, Bl, nullptr, nullptr, ROWS, EMB, EMB, part);
    splitk_reduce_kernel<<<(MN768 + 255)/256, 256>>>(part, a2_out_b, o, MN768, EMB, 3);
    // proj2: 2048x4096, K=768
    cvt(o, Ah, Al, ROWS*EMB);
    cvt(a2_proj_w, Bh, Bl, HW2*EMB);
    gemm_mma_kernel<1,0><<<dim3(32, 16, 1), 256, GMM_SMEM>>>(
        Ah, Al, Bh, Bl, a2_proj_b, y2, ROWS, HW2, EMB, nullptr);

    // --- head
    // fc1: 2048x2048, K=4096, fused relu
    cvt(y2, Ah, Al, ROWS*HW2);
    cvt(fc1_w, Bh, Bl, HC2*HW2);
    gemm_mma_kernel<1,1><<<dim3(16, 16, 1), 256, GMM_SMEM>>>(
        Ah, Al, Bh, Bl, fc1_b, h1, ROWS, HC2, HW2, nullptr);
    fc2_kernel<<<(ROWS*32 + 255)/256, 256>>>(h1, fc2_w, fc2_b, tp);
    params_kernel<<<(ROWS + 255)/256, 256>>>(tp, par, out_translate);
    gridsample_kernel<<<(ROWS*CIN*PSZ*PSZ + 255)/256, 256>>>(x, par, out_patches);
}